// round 11
// baseline (speedup 1.0000x reference)
#include <cuda_runtime.h>
#include <cuda_bf16.h>

#define B_  4
#define S_  512
#define D_  512
#define H_  16
#define DH_ 32
#define E_  128

typedef unsigned long long ull;

// ---- f32x2 packed-math helpers (sm_103a FFMA2 path, PTX-only) -------------
__device__ __forceinline__ ull pack2(float x, float y) {
    ull r; asm("mov.b64 %0, {%1, %2};" : "=l"(r) : "f"(x), "f"(y)); return r;
}
__device__ __forceinline__ void ffma2(ull& d, ull a, ull b) {
    asm("fma.rn.f32x2 %0, %1, %2, %0;" : "+l"(d) : "l"(a), "l"(b));
}
__device__ __forceinline__ ull fmul2(ull a, ull b) {
    ull r; asm("mul.rn.f32x2 %0, %1, %2;" : "=l"(r) : "l"(a), "l"(b)); return r;
}
__device__ __forceinline__ float2 unpack2(ull v) {
    float2 f; asm("mov.b64 {%0, %1}, %2;" : "=f"(f.x), "=f"(f.y) : "l"(v)); return f;
}

// scale * log2(e): scores pre-multiplied so softmax uses exp2f directly.
#define SCALE_L2E (0.10206207261596576f * 1.4426950408889634f)

// fp32 scratch (static device globals; no allocation anywhere)
__device__ float g_Q[B_*H_*S_*DH_];
__device__ float g_K[B_*H_*S_*DH_];
__device__ float g_V[B_*H_*S_*DH_];
__device__ float g_ksum[B_*H_*S_];
__device__ float g_qsum[B_*H_*S_];
__device__ float g_RADD[B_*H_*S_*S_];      // folded edge term * SCALE_L2E, [b,h,i,j]

// ---------------------------------------------------------------------------
// Kernel A: qkv = x @ Wqkv + bqkv  (M=2048, K=512, N=1536). Double-buffered
// 128x128x8 sgemm, FFMA2 inner product.
// ---------------------------------------------------------------------------
__global__ void __launch_bounds__(256) qkv_gemm_kernel(
    const float* __restrict__ X, const float* __restrict__ W,
    const float* __restrict__ bias)
{
    __shared__ __align__(16) float As[2][8 * 132];
    __shared__ __align__(16) float Bs[2][8 * 128];

    const int m0 = blockIdx.y * 128;
    const int n0 = blockIdx.x * 128;
    const int tid = threadIdx.x;
    const int tx = tid & 15;
    const int ty = tid >> 4;

    const int lm  = tid >> 1;
    const int lkq = (tid & 1) * 4;
    const int lkr = tid >> 5;
    const int lnq = (tid & 31) * 4;

    const float* Ag = X + (size_t)(m0 + lm) * 512 + lkq;
    const float* Bg = W + (size_t)lkr * 1536 + n0 + lnq;

    ull acc2[8][4];
#pragma unroll
    for (int i = 0; i < 8; i++)
#pragma unroll
        for (int j = 0; j < 4; j++) acc2[i][j] = 0ULL;

    {
        float4 av = *(const float4*)(Ag);
        float4 bv = *(const float4*)(Bg);
        As[0][(lkq + 0) * 132 + lm] = av.x;
        As[0][(lkq + 1) * 132 + lm] = av.y;
        As[0][(lkq + 2) * 132 + lm] = av.z;
        As[0][(lkq + 3) * 132 + lm] = av.w;
        *(float4*)(&Bs[0][lkr * 128 + lnq]) = bv;
    }
    __syncthreads();

    int buf = 0;
    for (int k0 = 0; k0 < 512; k0 += 8) {
        const bool has_next = (k0 + 8) < 512;
        float4 av, bv;
        if (has_next) {
            av = *(const float4*)(Ag + k0 + 8);
            bv = *(const float4*)(Bg + (size_t)(k0 + 8) * 1536);
        }

        const float* Asb = As[buf];
        const float* Bsb = Bs[buf];
#pragma unroll
        for (int kk = 0; kk < 8; kk++) {
            float a[8];
            *(float4*)(a)     = *(const float4*)(Asb + kk * 132 + ty * 8);
            *(float4*)(a + 4) = *(const float4*)(Asb + kk * 132 + ty * 8 + 4);
            ulonglong2 b01 = *(const ulonglong2*)(Bsb + kk * 128 + tx * 8);
            ulonglong2 b23 = *(const ulonglong2*)(Bsb + kk * 128 + tx * 8 + 4);
            ull bp0 = b01.x, bp1 = b01.y, bp2 = b23.x, bp3 = b23.y;
#pragma unroll
            for (int i = 0; i < 8; i++) {
                const ull ap = pack2(a[i], a[i]);
                ffma2(acc2[i][0], ap, bp0);
                ffma2(acc2[i][1], ap, bp1);
                ffma2(acc2[i][2], ap, bp2);
                ffma2(acc2[i][3], ap, bp3);
            }
        }

        if (has_next) {
            const int nb = buf ^ 1;
            As[nb][(lkq + 0) * 132 + lm] = av.x;
            As[nb][(lkq + 1) * 132 + lm] = av.y;
            As[nb][(lkq + 2) * 132 + lm] = av.z;
            As[nb][(lkq + 3) * 132 + lm] = av.w;
            *(float4*)(&Bs[nb][lkr * 128 + lnq]) = bv;
            __syncthreads();
            buf = nb;
        }
    }

#pragma unroll
    for (int i = 0; i < 8; i++) {
        const int m = m0 + ty * 8 + i;
        const int bb = m >> 9;
        const int s  = m & 511;
#pragma unroll
        for (int jp = 0; jp < 4; jp++) {
            const float2 vv = unpack2(acc2[i][jp]);
            const float vs[2] = {vv.x, vv.y};
#pragma unroll
            for (int q = 0; q < 2; q++) {
                const int n = n0 + tx * 8 + jp * 2 + q;
                const int h  = n / 96;
                const int r  = n - h * 96;
                const int t3 = r >> 5;
                const int d  = r & 31;
                const float v = vs[q] + bias[n];
                float* dst = (t3 == 0) ? g_Q : ((t3 == 1) ? g_K : g_V);
                dst[((size_t)(bb * H_ + h) * S_ + s) * DH_ + d] = v;
            }
        }
    }
}

// ---------------------------------------------------------------------------
// Kernel A2: qsum/ksum over dh.
// ---------------------------------------------------------------------------
__global__ void __launch_bounds__(256) sums_kernel()
{
    const int r = blockIdx.x * 256 + threadIdx.x;
    const float4* q4 = (const float4*)(g_Q + (size_t)r * DH_);
    const float4* k4 = (const float4*)(g_K + (size_t)r * DH_);
    float sq = 0.0f, sk = 0.0f;
#pragma unroll
    for (int u = 0; u < 8; u++) {
        float4 a = q4[u]; sq += (a.x + a.y) + (a.z + a.w);
        float4 c = k4[u]; sk += (c.x + c.y) + (c.z + c.w);
    }
    g_qsum[r] = sq;
    g_ksum[r] = sk;
}

// ---------------------------------------------------------------------------
// Kernel B: folded edge projection (output pre-scaled by SCALE_L2E).
// CTA = (b, i) full 512-j row, 256 threads, 8 chunks of 64 j.
// Register-prefetch pipeline: LDG chunk c+1 in flight during chunk-c compute.
// Thread = 1 j x 4 heads (hg warp-uniform -> Wc LDS.128 is broadcast).
// ---------------------------------------------------------------------------
__global__ void __launch_bounds__(256) radd_kernel(
    const float* __restrict__ P, const float* __restrict__ Wrqk,
    const float* __restrict__ brqk)
{
    __shared__ __align__(16) float pT[128 * 65];   // [e][j], conflict-free (33.3 KB)
    __shared__ __align__(16) float Wc[128 * 16];   // folded weights [e][h] (8 KB)
    __shared__ float kss[16], qss[16], badd[16];

    const int i  = blockIdx.x;
    const int b  = blockIdx.y;
    const int tid = threadIdx.x;

    if (tid < 16) {
        kss[tid] = g_ksum[(size_t)(b * H_ + tid) * S_ + i];
        qss[tid] = g_qsum[(size_t)(b * H_ + tid) * S_ + i];
    }
    __syncthreads();

    // folded weights + bias (once per (b,i) row)
#pragma unroll
    for (int u = 0; u < 8; u++) {
        const int f = tid + u * 256;
        const int e = f >> 4;
        const int h = f & 15;
        Wc[f] = Wrqk[e * 32 + 2 * h] * kss[h] + Wrqk[e * 32 + 2 * h + 1] * qss[h];
    }
    if (tid < 16)
        badd[tid] = brqk[2 * tid] * kss[tid] + brqk[2 * tid + 1] * qss[tid];

    const float4* pg4 = (const float4*)(P + ((size_t)(b * S_ + i)) * S_ * E_);

    // stage chunk 0: 64j x 128e = 2048 float4, 8 per thread
    {
#pragma unroll
        for (int u = 0; u < 8; u++) {
            const int f4 = tid + u * 256;
            const float4 v = pg4[f4];
            const int j  = f4 >> 5;
            const int e0 = (f4 & 31) * 4;
            pT[(e0 + 0) * 65 + j] = v.x;
            pT[(e0 + 1) * 65 + j] = v.y;
            pT[(e0 + 2) * 65 + j] = v.z;
            pT[(e0 + 3) * 65 + j] = v.w;
        }
    }
    __syncthreads();

    const int jg = tid & 63;     // j within chunk
    const int hg = tid >> 6;     // 0..3 -> heads hg*4 .. hg*4+3 (warp-uniform)

    for (int c = 0; c < 8; c++) {
        const bool hasn = (c < 7);
        float4 pr[8];
        if (hasn) {
#pragma unroll
            for (int u = 0; u < 8; u++)
                pr[u] = pg4[(c + 1) * 2048 + tid + u * 256];
        }

        ull acc2[2];
        acc2[0] = 0ULL; acc2[1] = 0ULL;

#pragma unroll 4
        for (int e = 0; e < 128; e++) {
            const float pv = pT[e * 65 + jg];
            const ull pp = pack2(pv, pv);
            const ulonglong2 w01 = *(const ulonglong2*)(Wc + e * 16 + hg * 4);
            ffma2(acc2[0], pp, w01.x);
            ffma2(acc2[1], pp, w01.y);
        }

        const int jglob = c * 64 + jg;
#pragma unroll
        for (int k = 0; k < 2; k++) {
            const float2 v = unpack2(acc2[k]);
            const int h0 = hg * 4 + 2 * k;
            const int h1 = h0 + 1;
            g_RADD[((size_t)(b * H_ + h0) * S_ + i) * S_ + jglob] = (v.x + badd[h0]) * SCALE_L2E;
            g_RADD[((size_t)(b * H_ + h1) * S_ + i) * S_ + jglob] = (v.y + badd[h1]) * SCALE_L2E;
        }

        if (hasn) {
            __syncthreads();   // all reads of pT for chunk c done
#pragma unroll
            for (int u = 0; u < 8; u++) {
                const int f4 = tid + u * 256;
                const int j  = f4 >> 5;
                const int e0 = (f4 & 31) * 4;
                pT[(e0 + 0) * 65 + j] = pr[u].x;
                pT[(e0 + 1) * 65 + j] = pr[u].y;
                pT[(e0 + 2) * 65 + j] = pr[u].z;
                pT[(e0 + 3) * 65 + j] = pr[u].w;
            }
            __syncthreads();   // new chunk visible
        }
    }
}

// ---------------------------------------------------------------------------
// Kernel C: fused attention. QK 4i x 4j microtile, softmax fully in
// registers (half-warp shuffles; QK i-ownership == PV i-ownership so m/l/α
// never leave the thread). Probs hit smem exactly once. 3 barriers/tile.
// ---------------------------------------------------------------------------
__global__ void __launch_bounds__(256) attn_kernel(
    const int* __restrict__ mask, float* __restrict__ out)
{
    __shared__ __align__(16) float q_s[32 * 68];   // [d][i], pre-scaled by SCALE_L2E
    __shared__ __align__(16) float k_s[32 * 68];   // [d][j]
    __shared__ __align__(16) float v_s[32 * 68];   // [d][j]
    __shared__ __align__(16) float s_s[64 * 68];   // [i][j] probs only

    const int b  = blockIdx.z;
    const int h  = blockIdx.y;
    const int i0 = blockIdx.x * 64;
    const int tid  = threadIdx.x;
    const int tx = tid & 15;        // j-group (QK) / d-pair (PV)
    const int ty = tid >> 4;        // i-group: rows ty*4 .. ty*4+3 (QK AND PV)

    const float maskvalL = -10000.0f * SCALE_L2E;

    const size_t bh = (size_t)(b * H_ + h);
    const float* kg_base = g_K + (bh * S_) * DH_;
    const float* vg_base = g_V + (bh * S_) * DH_;

    // load q tile transposed, pre-scaled
    {
        const float* qg = g_Q + (bh * S_ + i0) * DH_;
#pragma unroll
        for (int u = 0; u < 8; u++) {
            const int f = tid + u * 256;
            const int i = f >> 5;
            const int d = f & 31;
            q_s[d * 68 + i] = qg[f] * SCALE_L2E;
        }
    }

    // stage tile 0 (k,v transposed)
    {
        const float4* kg4 = (const float4*)kg_base;
        const float4* vg4 = (const float4*)vg_base;
#pragma unroll
        for (int u = 0; u < 2; u++) {
            const int f4 = tid + u * 256;
            const int j  = f4 >> 3;
            const int d0 = (f4 & 7) * 4;
            const float4 kv = kg4[f4];
            const float4 vv = vg4[f4];
            k_s[(d0 + 0) * 68 + j] = kv.x;
            k_s[(d0 + 1) * 68 + j] = kv.y;
            k_s[(d0 + 2) * 68 + j] = kv.z;
            k_s[(d0 + 3) * 68 + j] = kv.w;
            v_s[(d0 + 0) * 68 + j] = vv.x;
            v_s[(d0 + 1) * 68 + j] = vv.y;
            v_s[(d0 + 2) * 68 + j] = vv.z;
            v_s[(d0 + 3) * 68 + j] = vv.w;
        }
    }
    __syncthreads();

    float m4[4], l4[4];
#pragma unroll
    for (int ii = 0; ii < 4; ii++) { m4[ii] = -1e30f; l4[ii] = 0.0f; }

    ull accJ[4][2];                 // PV accumulators: [i-sub][d-sub]
#pragma unroll
    for (int a = 0; a < 4; a++) { accJ[a][0] = 0ULL; accJ[a][1] = 0ULL; }

    for (int t = 0; t < 8; t++) {
        const int j0 = t * 64;
        const bool hasn = (t < 7);

        // prefetch next k/v tile into registers
        float4 kr[2], vr[2];
        if (hasn) {
            const float4* kg4 = (const float4*)(kg_base + (size_t)(j0 + 64) * DH_);
            const float4* vg4 = (const float4*)(vg_base + (size_t)(j0 + 64) * DH_);
#pragma unroll
            for (int u = 0; u < 2; u++) {
                kr[u] = kg4[tid + u * 256];
                vr[u] = vg4[tid + u * 256];
            }
        }

        // prefetch RADD + mask (consumed after QK)
        float4 r4[4]; int4 mk[4];
#pragma unroll
        for (int ii = 0; ii < 4; ii++) {
            const int i = i0 + ty * 4 + ii;
            r4[ii] = *(const float4*)(g_RADD + (bh * S_ + i) * S_ + j0 + tx * 4);
            mk[ii] = *(const int4*)(mask + ((size_t)(b * S_ + i)) * S_ + j0 + tx * 4);
        }

        // --- QK^T 64x64, FFMA2 pairs over j ---
        ull acc2[4][2];
#pragma unroll
        for (int a = 0; a < 4; a++) { acc2[a][0] = 0ULL; acc2[a][1] = 0ULL; }

#pragma unroll
        for (int d = 0; d < 32; d++) {
            float av[4];
            *(float4*)(av) = *(const float4*)(q_s + d * 68 + ty * 4);
            const ulonglong2 bq = *(const ulonglong2*)(k_s + d * 68 + tx * 4);
#pragma unroll
            for (int ii = 0; ii < 4; ii++) {
                const ull ap = pack2(av[ii], av[ii]);
                ffma2(acc2[ii][0], ap, bq.x);
                ffma2(acc2[ii][1], ap, bq.y);
            }
        }

        // --- softmax fully in registers (reduce across the 16-lane j-group) ---
#pragma unroll
        for (int ii = 0; ii < 4; ii++) {
            const float2 p01 = unpack2(acc2[ii][0]);
            const float2 p23 = unpack2(acc2[ii][1]);
            float x0 = (mk[ii].x != 0) ? (p01.x + r4[ii].x) : maskvalL;
            float x1 = (mk[ii].y != 0) ? (p01.y + r4[ii].y) : maskvalL;
            float x2 = (mk[ii].z != 0) ? (p23.x + r4[ii].z) : maskvalL;
            float x3 = (mk[ii].w != 0) ? (p23.y + r4[ii].w) : maskvalL;

            float mx = fmaxf(fmaxf(x0, x1), fmaxf(x2, x3));
#pragma unroll
            for (int off = 8; off > 0; off >>= 1)   // xor<=8 stays in 16-lane half
                mx = fmaxf(mx, __shfl_xor_sync(0xffffffffu, mx, off));

            const float m_new = fmaxf(m4[ii], mx);
            const float e0 = exp2f(x0 - m_new);
            const float e1 = exp2f(x1 - m_new);
            const float e2 = exp2f(x2 - m_new);
            const float e3 = exp2f(x3 - m_new);

            float sm = (e0 + e1) + (e2 + e3);
#pragma unroll
            for (int off = 8; off > 0; off >>= 1)
                sm += __shfl_xor_sync(0xffffffffu, sm, off);

            const float alpha = exp2f(m4[ii] - m_new);
            l4[ii] = l4[ii] * alpha + sm;
            m4[ii] = m_new;

            // rescale this row's PV accumulator (same-thread ownership)
            const ull ap = pack2(alpha, alpha);
            accJ[ii][0] = fmul2(accJ[ii][0], ap);
            accJ[ii][1] = fmul2(accJ[ii][1], ap);

            // probs to smem (single touch)
            *(float4*)(s_s + (ty * 4 + ii) * 68 + tx * 4) = make_float4(e0, e1, e2, e3);
        }
        __syncthreads();   // probs visible; QK done CTA-wide

        // --- PV: thread = 4i x 2d, FFMA2 packed over (even j, odd j) ---
        const int ib = ty * 4;
        const int d0 = tx * 2;
#pragma unroll 4
        for (int j4 = 0; j4 < 64; j4 += 4) {
            const ulonglong2 v0 = *(const ulonglong2*)(v_s + (d0 + 0) * 68 + j4);
            const ulonglong2 v1 = *(const ulonglong2*)(v_s + (d0 + 1) * 68 + j4);
#pragma unroll
            for (int ii = 0; ii < 4; ii++) {
                const ulonglong2 pp = *(const ulonglong2*)(s_s + (ib + ii) * 68 + j4);
                ffma2(accJ[ii][0], pp.x, v0.x);
                ffma2(accJ[ii][0], pp.y, v0.y);
                ffma2(accJ[ii][1], pp.x, v1.x);
                ffma2(accJ[ii][1], pp.y, v1.y);
            }
        }

        if (hasn) {
            __syncthreads();   // all reads of k_s/v_s/s_s done
#pragma unroll
            for (int u = 0; u < 2; u++) {
                const int f4 = tid + u * 256;
                const int j  = f4 >> 3;
                const int dd = (f4 & 7) * 4;
                k_s[(dd + 0) * 68 + j] = kr[u].x;
                k_s[(dd + 1) * 68 + j] = kr[u].y;
                k_s[(dd + 2) * 68 + j] = kr[u].z;
                k_s[(dd + 3) * 68 + j] = kr[u].w;
                v_s[(dd + 0) * 68 + j] = vr[u].x;
                v_s[(dd + 1) * 68 + j] = vr[u].y;
                v_s[(dd + 2) * 68 + j] = vr[u].z;
                v_s[(dd + 3) * 68 + j] = vr[u].w;
            }
            __syncthreads();   // new tile visible
        }
    }

    // epilogue: l lives in-thread (replicated across the 16-lane j-group)
    const int ib = ty * 4;
    const int d0 = tx * 2;
#pragma unroll
    for (int ii = 0; ii < 4; ii++) {
        const float inv = 1.0f / l4[ii];
        const float2 o0 = unpack2(accJ[ii][0]);
        const float2 o1 = unpack2(accJ[ii][1]);
        float2 res;
        res.x = (o0.x + o0.y) * inv;
        res.y = (o1.x + o1.y) * inv;
        *(float2*)(out + ((size_t)(b * S_ + i0 + ib + ii)) * D_ + h * DH_ + d0) = res;
    }
}

// ---------------------------------------------------------------------------
extern "C" void kernel_launch(void* const* d_in, const int* in_sizes, int n_in,
                              void* d_out, int out_size)
{
    const float* x     = (const float*)d_in[0];
    const float* p     = (const float*)d_in[1];
    const int*   mask  = (const int*)  d_in[2];
    const float* Wqkv  = (const float*)d_in[3];
    const float* bqkv  = (const float*)d_in[4];
    const float* Wrqk  = (const float*)d_in[5];
    const float* brqk  = (const float*)d_in[6];
    float* out = (float*)d_out;

    (void)in_sizes; (void)n_in; (void)out_size;

    qkv_gemm_kernel<<<dim3(1536 / 128, 2048 / 128), 256>>>(x, Wqkv, bqkv);
    sums_kernel<<<(B_ * H_ * S_) / 256, 256>>>();
    radd_kernel<<<dim3(S_, B_), 256>>>(p, Wrqk, brqk);
    attn_kernel<<<dim3(S_ / 64, H_, B_), 256>>>(mask, out);
}

// round 12
// speedup vs baseline: 1.0037x; 1.0037x over previous
#include <cuda_runtime.h>
#include <cuda_bf16.h>

#define B_  4
#define S_  512
#define D_  512
#define H_  16
#define DH_ 32
#define E_  128

typedef unsigned long long ull;

// ---- f32x2 packed-math helpers (sm_103a FFMA2 path, PTX-only) -------------
__device__ __forceinline__ ull pack2(float x, float y) {
    ull r; asm("mov.b64 %0, {%1, %2};" : "=l"(r) : "f"(x), "f"(y)); return r;
}
__device__ __forceinline__ void ffma2(ull& d, ull a, ull b) {
    asm("fma.rn.f32x2 %0, %1, %2, %0;" : "+l"(d) : "l"(a), "l"(b));
}
__device__ __forceinline__ ull fmul2(ull a, ull b) {
    ull r; asm("mul.rn.f32x2 %0, %1, %2;" : "=l"(r) : "l"(a), "l"(b)); return r;
}
__device__ __forceinline__ float2 unpack2(ull v) {
    float2 f; asm("mov.b64 {%0, %1}, %2;" : "=f"(f.x), "=f"(f.y) : "l"(v)); return f;
}

// scale * log2(e): scores pre-multiplied so softmax uses exp2f directly.
#define SCALE_L2E (0.10206207261596576f * 1.4426950408889634f)

// fp32 scratch (static device globals; no allocation anywhere)
__device__ float g_Q[B_*H_*S_*DH_];
__device__ float g_K[B_*H_*S_*DH_];
__device__ float g_V[B_*H_*S_*DH_];
__device__ float g_ksum[B_*H_*S_];
__device__ float g_qsum[B_*H_*S_];
__device__ float g_RADD[B_*H_*S_*S_];      // folded edge term * SCALE_L2E, [b,h,i,j]

// ---------------------------------------------------------------------------
// Kernel A: qkv = x @ Wqkv + bqkv  (M=2048, K=512, N=1536). Double-buffered
// 128x128x8 sgemm, FFMA2 inner product.
// ---------------------------------------------------------------------------
__global__ void __launch_bounds__(256) qkv_gemm_kernel(
    const float* __restrict__ X, const float* __restrict__ W,
    const float* __restrict__ bias)
{
    __shared__ __align__(16) float As[2][8 * 132];
    __shared__ __align__(16) float Bs[2][8 * 128];

    const int m0 = blockIdx.y * 128;
    const int n0 = blockIdx.x * 128;
    const int tid = threadIdx.x;
    const int tx = tid & 15;
    const int ty = tid >> 4;

    const int lm  = tid >> 1;
    const int lkq = (tid & 1) * 4;
    const int lkr = tid >> 5;
    const int lnq = (tid & 31) * 4;

    const float* Ag = X + (size_t)(m0 + lm) * 512 + lkq;
    const float* Bg = W + (size_t)lkr * 1536 + n0 + lnq;

    ull acc2[8][4];
#pragma unroll
    for (int i = 0; i < 8; i++)
#pragma unroll
        for (int j = 0; j < 4; j++) acc2[i][j] = 0ULL;

    {
        float4 av = *(const float4*)(Ag);
        float4 bv = *(const float4*)(Bg);
        As[0][(lkq + 0) * 132 + lm] = av.x;
        As[0][(lkq + 1) * 132 + lm] = av.y;
        As[0][(lkq + 2) * 132 + lm] = av.z;
        As[0][(lkq + 3) * 132 + lm] = av.w;
        *(float4*)(&Bs[0][lkr * 128 + lnq]) = bv;
    }
    __syncthreads();

    int buf = 0;
    for (int k0 = 0; k0 < 512; k0 += 8) {
        const bool has_next = (k0 + 8) < 512;
        float4 av, bv;
        if (has_next) {
            av = *(const float4*)(Ag + k0 + 8);
            bv = *(const float4*)(Bg + (size_t)(k0 + 8) * 1536);
        }

        const float* Asb = As[buf];
        const float* Bsb = Bs[buf];
#pragma unroll
        for (int kk = 0; kk < 8; kk++) {
            float a[8];
            *(float4*)(a)     = *(const float4*)(Asb + kk * 132 + ty * 8);
            *(float4*)(a + 4) = *(const float4*)(Asb + kk * 132 + ty * 8 + 4);
            ulonglong2 b01 = *(const ulonglong2*)(Bsb + kk * 128 + tx * 8);
            ulonglong2 b23 = *(const ulonglong2*)(Bsb + kk * 128 + tx * 8 + 4);
            ull bp0 = b01.x, bp1 = b01.y, bp2 = b23.x, bp3 = b23.y;
#pragma unroll
            for (int i = 0; i < 8; i++) {
                const ull ap = pack2(a[i], a[i]);
                ffma2(acc2[i][0], ap, bp0);
                ffma2(acc2[i][1], ap, bp1);
                ffma2(acc2[i][2], ap, bp2);
                ffma2(acc2[i][3], ap, bp3);
            }
        }

        if (has_next) {
            const int nb = buf ^ 1;
            As[nb][(lkq + 0) * 132 + lm] = av.x;
            As[nb][(lkq + 1) * 132 + lm] = av.y;
            As[nb][(lkq + 2) * 132 + lm] = av.z;
            As[nb][(lkq + 3) * 132 + lm] = av.w;
            *(float4*)(&Bs[nb][lkr * 128 + lnq]) = bv;
            __syncthreads();
            buf = nb;
        }
    }

#pragma unroll
    for (int i = 0; i < 8; i++) {
        const int m = m0 + ty * 8 + i;
        const int bb = m >> 9;
        const int s  = m & 511;
#pragma unroll
        for (int jp = 0; jp < 4; jp++) {
            const float2 vv = unpack2(acc2[i][jp]);
            const float vs[2] = {vv.x, vv.y};
#pragma unroll
            for (int q = 0; q < 2; q++) {
                const int n = n0 + tx * 8 + jp * 2 + q;
                const int h  = n / 96;
                const int r  = n - h * 96;
                const int t3 = r >> 5;
                const int d  = r & 31;
                const float v = vs[q] + bias[n];
                float* dst = (t3 == 0) ? g_Q : ((t3 == 1) ? g_K : g_V);
                dst[((size_t)(bb * H_ + h) * S_ + s) * DH_ + d] = v;
            }
        }
    }
}

// ---------------------------------------------------------------------------
// Kernel A2: qsum/ksum over dh.
// ---------------------------------------------------------------------------
__global__ void __launch_bounds__(256) sums_kernel()
{
    const int r = blockIdx.x * 256 + threadIdx.x;
    const float4* q4 = (const float4*)(g_Q + (size_t)r * DH_);
    const float4* k4 = (const float4*)(g_K + (size_t)r * DH_);
    float sq = 0.0f, sk = 0.0f;
#pragma unroll
    for (int u = 0; u < 8; u++) {
        float4 a = q4[u]; sq += (a.x + a.y) + (a.z + a.w);
        float4 c = k4[u]; sk += (c.x + c.y) + (c.z + c.w);
    }
    g_qsum[r] = sq;
    g_ksum[r] = sk;
}

// ---------------------------------------------------------------------------
// Kernel B: folded edge projection (output pre-scaled by SCALE_L2E).
// CTA = (b, i) full 512-j row, 256 threads, 8 chunks of 64 j.
// Register-prefetch pipeline: LDG chunk c+1 in flight during chunk-c compute.
// Thread = 1 j x 4 heads (hg warp-uniform -> Wc LDS.128 is broadcast).
// ---------------------------------------------------------------------------
__global__ void __launch_bounds__(256) radd_kernel(
    const float* __restrict__ P, const float* __restrict__ Wrqk,
    const float* __restrict__ brqk)
{
    __shared__ __align__(16) float pT[128 * 65];   // [e][j], conflict-free (33.3 KB)
    __shared__ __align__(16) float Wc[128 * 16];   // folded weights [e][h] (8 KB)
    __shared__ float kss[16], qss[16], badd[16];

    const int i  = blockIdx.x;
    const int b  = blockIdx.y;
    const int tid = threadIdx.x;

    if (tid < 16) {
        kss[tid] = g_ksum[(size_t)(b * H_ + tid) * S_ + i];
        qss[tid] = g_qsum[(size_t)(b * H_ + tid) * S_ + i];
    }
    __syncthreads();

    // folded weights + bias (once per (b,i) row)
#pragma unroll
    for (int u = 0; u < 8; u++) {
        const int f = tid + u * 256;
        const int e = f >> 4;
        const int h = f & 15;
        Wc[f] = Wrqk[e * 32 + 2 * h] * kss[h] + Wrqk[e * 32 + 2 * h + 1] * qss[h];
    }
    if (tid < 16)
        badd[tid] = brqk[2 * tid] * kss[tid] + brqk[2 * tid + 1] * qss[tid];

    const float4* pg4 = (const float4*)(P + ((size_t)(b * S_ + i)) * S_ * E_);

    // stage chunk 0: 64j x 128e = 2048 float4, 8 per thread
    {
#pragma unroll
        for (int u = 0; u < 8; u++) {
            const int f4 = tid + u * 256;
            const float4 v = pg4[f4];
            const int j  = f4 >> 5;
            const int e0 = (f4 & 31) * 4;
            pT[(e0 + 0) * 65 + j] = v.x;
            pT[(e0 + 1) * 65 + j] = v.y;
            pT[(e0 + 2) * 65 + j] = v.z;
            pT[(e0 + 3) * 65 + j] = v.w;
        }
    }
    __syncthreads();

    const int jg = tid & 63;     // j within chunk
    const int hg = tid >> 6;     // 0..3 -> heads hg*4 .. hg*4+3 (warp-uniform)

    for (int c = 0; c < 8; c++) {
        const bool hasn = (c < 7);
        float4 pr[8];
        if (hasn) {
#pragma unroll
            for (int u = 0; u < 8; u++)
                pr[u] = pg4[(c + 1) * 2048 + tid + u * 256];
        }

        ull acc2[2];
        acc2[0] = 0ULL; acc2[1] = 0ULL;

#pragma unroll 4
        for (int e = 0; e < 128; e++) {
            const float pv = pT[e * 65 + jg];
            const ull pp = pack2(pv, pv);
            const ulonglong2 w01 = *(const ulonglong2*)(Wc + e * 16 + hg * 4);
            ffma2(acc2[0], pp, w01.x);
            ffma2(acc2[1], pp, w01.y);
        }

        const int jglob = c * 64 + jg;
#pragma unroll
        for (int k = 0; k < 2; k++) {
            const float2 v = unpack2(acc2[k]);
            const int h0 = hg * 4 + 2 * k;
            const int h1 = h0 + 1;
            g_RADD[((size_t)(b * H_ + h0) * S_ + i) * S_ + jglob] = (v.x + badd[h0]) * SCALE_L2E;
            g_RADD[((size_t)(b * H_ + h1) * S_ + i) * S_ + jglob] = (v.y + badd[h1]) * SCALE_L2E;
        }

        if (hasn) {
            __syncthreads();   // all reads of pT for chunk c done
#pragma unroll
            for (int u = 0; u < 8; u++) {
                const int f4 = tid + u * 256;
                const int j  = f4 >> 5;
                const int e0 = (f4 & 31) * 4;
                pT[(e0 + 0) * 65 + j] = pr[u].x;
                pT[(e0 + 1) * 65 + j] = pr[u].y;
                pT[(e0 + 2) * 65 + j] = pr[u].z;
                pT[(e0 + 3) * 65 + j] = pr[u].w;
            }
            __syncthreads();   // new chunk visible
        }
    }
}

// ---------------------------------------------------------------------------
// Kernel C: fused attention. QK 4i x 4j microtile, softmax fully in
// registers (half-warp shuffles; QK i-ownership == PV i-ownership so m/l/α
// never leave the thread). Probs hit smem exactly once. 3 barriers/tile.
// ---------------------------------------------------------------------------
__global__ void __launch_bounds__(256) attn_kernel(
    const int* __restrict__ mask, float* __restrict__ out)
{
    __shared__ __align__(16) float q_s[32 * 68];   // [d][i], pre-scaled by SCALE_L2E
    __shared__ __align__(16) float k_s[32 * 68];   // [d][j]
    __shared__ __align__(16) float v_s[32 * 68];   // [d][j]
    __shared__ __align__(16) float s_s[64 * 68];   // [i][j] probs only

    const int b  = blockIdx.z;
    const int h  = blockIdx.y;
    const int i0 = blockIdx.x * 64;
    const int tid  = threadIdx.x;
    const int tx = tid & 15;        // j-group (QK) / d-pair (PV)
    const int ty = tid >> 4;        // i-group: rows ty*4 .. ty*4+3 (QK AND PV)

    const float maskvalL = -10000.0f * SCALE_L2E;

    const size_t bh = (size_t)(b * H_ + h);
    const float* kg_base = g_K + (bh * S_) * DH_;
    const float* vg_base = g_V + (bh * S_) * DH_;

    // load q tile transposed, pre-scaled
    {
        const float* qg = g_Q + (bh * S_ + i0) * DH_;
#pragma unroll
        for (int u = 0; u < 8; u++) {
            const int f = tid + u * 256;
            const int i = f >> 5;
            const int d = f & 31;
            q_s[d * 68 + i] = qg[f] * SCALE_L2E;
        }
    }

    // stage tile 0 (k,v transposed)
    {
        const float4* kg4 = (const float4*)kg_base;
        const float4* vg4 = (const float4*)vg_base;
#pragma unroll
        for (int u = 0; u < 2; u++) {
            const int f4 = tid + u * 256;
            const int j  = f4 >> 3;
            const int d0 = (f4 & 7) * 4;
            const float4 kv = kg4[f4];
            const float4 vv = vg4[f4];
            k_s[(d0 + 0) * 68 + j] = kv.x;
            k_s[(d0 + 1) * 68 + j] = kv.y;
            k_s[(d0 + 2) * 68 + j] = kv.z;
            k_s[(d0 + 3) * 68 + j] = kv.w;
            v_s[(d0 + 0) * 68 + j] = vv.x;
            v_s[(d0 + 1) * 68 + j] = vv.y;
            v_s[(d0 + 2) * 68 + j] = vv.z;
            v_s[(d0 + 3) * 68 + j] = vv.w;
        }
    }
    __syncthreads();

    float m4[4], l4[4];
#pragma unroll
    for (int ii = 0; ii < 4; ii++) { m4[ii] = -1e30f; l4[ii] = 0.0f; }

    ull accJ[4][2];                 // PV accumulators: [i-sub][d-sub]
#pragma unroll
    for (int a = 0; a < 4; a++) { accJ[a][0] = 0ULL; accJ[a][1] = 0ULL; }

    for (int t = 0; t < 8; t++) {
        const int j0 = t * 64;
        const bool hasn = (t < 7);

        // prefetch next k/v tile into registers
        float4 kr[2], vr[2];
        if (hasn) {
            const float4* kg4 = (const float4*)(kg_base + (size_t)(j0 + 64) * DH_);
            const float4* vg4 = (const float4*)(vg_base + (size_t)(j0 + 64) * DH_);
#pragma unroll
            for (int u = 0; u < 2; u++) {
                kr[u] = kg4[tid + u * 256];
                vr[u] = vg4[tid + u * 256];
            }
        }

        // prefetch RADD + mask (consumed after QK)
        float4 r4[4]; int4 mk[4];
#pragma unroll
        for (int ii = 0; ii < 4; ii++) {
            const int i = i0 + ty * 4 + ii;
            r4[ii] = *(const float4*)(g_RADD + (bh * S_ + i) * S_ + j0 + tx * 4);
            mk[ii] = *(const int4*)(mask + ((size_t)(b * S_ + i)) * S_ + j0 + tx * 4);
        }

        // --- QK^T 64x64, FFMA2 pairs over j ---
        ull acc2[4][2];
#pragma unroll
        for (int a = 0; a < 4; a++) { acc2[a][0] = 0ULL; acc2[a][1] = 0ULL; }

#pragma unroll
        for (int d = 0; d < 32; d++) {
            float av[4];
            *(float4*)(av) = *(const float4*)(q_s + d * 68 + ty * 4);
            const ulonglong2 bq = *(const ulonglong2*)(k_s + d * 68 + tx * 4);
#pragma unroll
            for (int ii = 0; ii < 4; ii++) {
                const ull ap = pack2(av[ii], av[ii]);
                ffma2(acc2[ii][0], ap, bq.x);
                ffma2(acc2[ii][1], ap, bq.y);
            }
        }

        // --- softmax fully in registers (reduce across the 16-lane j-group) ---
#pragma unroll
        for (int ii = 0; ii < 4; ii++) {
            const float2 p01 = unpack2(acc2[ii][0]);
            const float2 p23 = unpack2(acc2[ii][1]);
            float x0 = (mk[ii].x != 0) ? (p01.x + r4[ii].x) : maskvalL;
            float x1 = (mk[ii].y != 0) ? (p01.y + r4[ii].y) : maskvalL;
            float x2 = (mk[ii].z != 0) ? (p23.x + r4[ii].z) : maskvalL;
            float x3 = (mk[ii].w != 0) ? (p23.y + r4[ii].w) : maskvalL;

            float mx = fmaxf(fmaxf(x0, x1), fmaxf(x2, x3));
#pragma unroll
            for (int off = 8; off > 0; off >>= 1)   // xor<=8 stays in 16-lane half
                mx = fmaxf(mx, __shfl_xor_sync(0xffffffffu, mx, off));

            const float m_new = fmaxf(m4[ii], mx);
            const float e0 = exp2f(x0 - m_new);
            const float e1 = exp2f(x1 - m_new);
            const float e2 = exp2f(x2 - m_new);
            const float e3 = exp2f(x3 - m_new);

            float sm = (e0 + e1) + (e2 + e3);
#pragma unroll
            for (int off = 8; off > 0; off >>= 1)
                sm += __shfl_xor_sync(0xffffffffu, sm, off);

            const float alpha = exp2f(m4[ii] - m_new);
            l4[ii] = l4[ii] * alpha + sm;
            m4[ii] = m_new;

            // rescale this row's PV accumulator (same-thread ownership)
            const ull ap = pack2(alpha, alpha);
            accJ[ii][0] = fmul2(accJ[ii][0], ap);
            accJ[ii][1] = fmul2(accJ[ii][1], ap);

            // probs to smem (single touch)
            *(float4*)(s_s + (ty * 4 + ii) * 68 + tx * 4) = make_float4(e0, e1, e2, e3);
        }
        __syncthreads();   // probs visible; QK done CTA-wide

        // --- PV: thread = 4i x 2d, FFMA2 packed over (even j, odd j) ---
        const int ib = ty * 4;
        const int d0 = tx * 2;
#pragma unroll 4
        for (int j4 = 0; j4 < 64; j4 += 4) {
            const ulonglong2 v0 = *(const ulonglong2*)(v_s + (d0 + 0) * 68 + j4);
            const ulonglong2 v1 = *(const ulonglong2*)(v_s + (d0 + 1) * 68 + j4);
#pragma unroll
            for (int ii = 0; ii < 4; ii++) {
                const ulonglong2 pp = *(const ulonglong2*)(s_s + (ib + ii) * 68 + j4);
                ffma2(accJ[ii][0], pp.x, v0.x);
                ffma2(accJ[ii][0], pp.y, v0.y);
                ffma2(accJ[ii][1], pp.x, v1.x);
                ffma2(accJ[ii][1], pp.y, v1.y);
            }
        }

        if (hasn) {
            __syncthreads();   // all reads of k_s/v_s/s_s done
#pragma unroll
            for (int u = 0; u < 2; u++) {
                const int f4 = tid + u * 256;
                const int j  = f4 >> 3;
                const int dd = (f4 & 7) * 4;
                k_s[(dd + 0) * 68 + j] = kr[u].x;
                k_s[(dd + 1) * 68 + j] = kr[u].y;
                k_s[(dd + 2) * 68 + j] = kr[u].z;
                k_s[(dd + 3) * 68 + j] = kr[u].w;
                v_s[(dd + 0) * 68 + j] = vr[u].x;
                v_s[(dd + 1) * 68 + j] = vr[u].y;
                v_s[(dd + 2) * 68 + j] = vr[u].z;
                v_s[(dd + 3) * 68 + j] = vr[u].w;
            }
            __syncthreads();   // new tile visible
        }
    }

    // epilogue: l lives in-thread (replicated across the 16-lane j-group)
    const int ib = ty * 4;
    const int d0 = tx * 2;
#pragma unroll
    for (int ii = 0; ii < 4; ii++) {
        const float inv = 1.0f / l4[ii];
        const float2 o0 = unpack2(accJ[ii][0]);
        const float2 o1 = unpack2(accJ[ii][1]);
        float2 res;
        res.x = (o0.x + o0.y) * inv;
        res.y = (o1.x + o1.y) * inv;
        *(float2*)(out + ((size_t)(b * S_ + i0 + ib + ii)) * D_ + h * DH_ + d0) = res;
    }
}

// ---------------------------------------------------------------------------
extern "C" void kernel_launch(void* const* d_in, const int* in_sizes, int n_in,
                              void* d_out, int out_size)
{
    const float* x     = (const float*)d_in[0];
    const float* p     = (const float*)d_in[1];
    const int*   mask  = (const int*)  d_in[2];
    const float* Wqkv  = (const float*)d_in[3];
    const float* bqkv  = (const float*)d_in[4];
    const float* Wrqk  = (const float*)d_in[5];
    const float* brqk  = (const float*)d_in[6];
    float* out = (float*)d_out;

    (void)in_sizes; (void)n_in; (void)out_size;

    qkv_gemm_kernel<<<dim3(1536 / 128, 2048 / 128), 256>>>(x, Wqkv, bqkv);
    sums_kernel<<<(B_ * H_ * S_) / 256, 256>>>();
    radd_kernel<<<dim3(S_, B_), 256>>>(p, Wrqk, brqk);
    attn_kernel<<<dim3(S_ / 64, H_, B_), 256>>>(mask, out);
}

// round 13
// speedup vs baseline: 1.0344x; 1.0305x over previous
#include <cuda_runtime.h>
#include <cuda_bf16.h>

#define B_  4
#define S_  512
#define D_  512
#define H_  16
#define DH_ 32
#define E_  128

typedef unsigned long long ull;

// ---- f32x2 packed-math helpers (sm_103a FFMA2 path, PTX-only) -------------
__device__ __forceinline__ ull pack2(float x, float y) {
    ull r; asm("mov.b64 %0, {%1, %2};" : "=l"(r) : "f"(x), "f"(y)); return r;
}
__device__ __forceinline__ void ffma2(ull& d, ull a, ull b) {
    asm("fma.rn.f32x2 %0, %1, %2, %0;" : "+l"(d) : "l"(a), "l"(b));
}
__device__ __forceinline__ ull fmul2(ull a, ull b) {
    ull r; asm("mul.rn.f32x2 %0, %1, %2;" : "=l"(r) : "l"(a), "l"(b)); return r;
}
__device__ __forceinline__ float2 unpack2(ull v) {
    float2 f; asm("mov.b64 {%0, %1}, %2;" : "=f"(f.x), "=f"(f.y) : "l"(v)); return f;
}

// scale * log2(e): scores pre-multiplied so softmax uses exp2f directly.
#define SCALE_L2E (0.10206207261596576f * 1.4426950408889634f)
#define MASKED_SCORE (-1e30f)

// fp32 scratch (static device globals; no allocation anywhere)
__device__ float g_Q[B_*H_*S_*DH_];
__device__ float g_K[B_*H_*S_*DH_];
__device__ float g_V[B_*H_*S_*DH_];
__device__ float g_RADD[B_*H_*S_*S_];   // folded edge term * SCALE_L2E, mask folded in

// ---------------------------------------------------------------------------
// Kernel A: qkv = x @ Wqkv + bqkv  (M=2048, K=512, N=1536). Double-buffered
// 128x128x8 sgemm, FFMA2 inner product.
// ---------------------------------------------------------------------------
__global__ void __launch_bounds__(256) qkv_gemm_kernel(
    const float* __restrict__ X, const float* __restrict__ W,
    const float* __restrict__ bias)
{
    __shared__ __align__(16) float As[2][8 * 132];
    __shared__ __align__(16) float Bs[2][8 * 128];

    const int m0 = blockIdx.y * 128;
    const int n0 = blockIdx.x * 128;
    const int tid = threadIdx.x;
    const int tx = tid & 15;
    const int ty = tid >> 4;

    const int lm  = tid >> 1;
    const int lkq = (tid & 1) * 4;
    const int lkr = tid >> 5;
    const int lnq = (tid & 31) * 4;

    const float* Ag = X + (size_t)(m0 + lm) * 512 + lkq;
    const float* Bg = W + (size_t)lkr * 1536 + n0 + lnq;

    ull acc2[8][4];
#pragma unroll
    for (int i = 0; i < 8; i++)
#pragma unroll
        for (int j = 0; j < 4; j++) acc2[i][j] = 0ULL;

    {
        float4 av = *(const float4*)(Ag);
        float4 bv = *(const float4*)(Bg);
        As[0][(lkq + 0) * 132 + lm] = av.x;
        As[0][(lkq + 1) * 132 + lm] = av.y;
        As[0][(lkq + 2) * 132 + lm] = av.z;
        As[0][(lkq + 3) * 132 + lm] = av.w;
        *(float4*)(&Bs[0][lkr * 128 + lnq]) = bv;
    }
    __syncthreads();

    int buf = 0;
    for (int k0 = 0; k0 < 512; k0 += 8) {
        const bool has_next = (k0 + 8) < 512;
        float4 av, bv;
        if (has_next) {
            av = *(const float4*)(Ag + k0 + 8);
            bv = *(const float4*)(Bg + (size_t)(k0 + 8) * 1536);
        }

        const float* Asb = As[buf];
        const float* Bsb = Bs[buf];
#pragma unroll
        for (int kk = 0; kk < 8; kk++) {
            float a[8];
            *(float4*)(a)     = *(const float4*)(Asb + kk * 132 + ty * 8);
            *(float4*)(a + 4) = *(const float4*)(Asb + kk * 132 + ty * 8 + 4);
            ulonglong2 b01 = *(const ulonglong2*)(Bsb + kk * 128 + tx * 8);
            ulonglong2 b23 = *(const ulonglong2*)(Bsb + kk * 128 + tx * 8 + 4);
            ull bp0 = b01.x, bp1 = b01.y, bp2 = b23.x, bp3 = b23.y;
#pragma unroll
            for (int i = 0; i < 8; i++) {
                const ull ap = pack2(a[i], a[i]);
                ffma2(acc2[i][0], ap, bp0);
                ffma2(acc2[i][1], ap, bp1);
                ffma2(acc2[i][2], ap, bp2);
                ffma2(acc2[i][3], ap, bp3);
            }
        }

        if (has_next) {
            const int nb = buf ^ 1;
            As[nb][(lkq + 0) * 132 + lm] = av.x;
            As[nb][(lkq + 1) * 132 + lm] = av.y;
            As[nb][(lkq + 2) * 132 + lm] = av.z;
            As[nb][(lkq + 3) * 132 + lm] = av.w;
            *(float4*)(&Bs[nb][lkr * 128 + lnq]) = bv;
            __syncthreads();
            buf = nb;
        }
    }

#pragma unroll
    for (int i = 0; i < 8; i++) {
        const int m = m0 + ty * 8 + i;
        const int bb = m >> 9;
        const int s  = m & 511;
#pragma unroll
        for (int jp = 0; jp < 4; jp++) {
            const float2 vv = unpack2(acc2[i][jp]);
            const float vs[2] = {vv.x, vv.y};
#pragma unroll
            for (int q = 0; q < 2; q++) {
                const int n = n0 + tx * 8 + jp * 2 + q;
                const int h  = n / 96;
                const int r  = n - h * 96;
                const int t3 = r >> 5;
                const int d  = r & 31;
                const float v = vs[q] + bias[n];
                float* dst = (t3 == 0) ? g_Q : ((t3 == 1) ? g_K : g_V);
                dst[((size_t)(bb * H_ + h) * S_ + s) * DH_ + d] = v;
            }
        }
    }
}

// ---------------------------------------------------------------------------
// Kernel B: folded edge projection, mask folded in, sums fused inline.
// CTA = (b, i), 256 threads, 8 chunks of 64 j. Register-prefetch pipeline.
// Output: RADD[b,h,i,j] = mask ? (p.Wc + badd)*SCALE_L2E : -1e30
// ---------------------------------------------------------------------------
__global__ void __launch_bounds__(256) radd_kernel(
    const float* __restrict__ P, const float* __restrict__ Wrqk,
    const float* __restrict__ brqk, const int* __restrict__ mask)
{
    __shared__ __align__(16) float pT[128 * 65];   // [e][j], conflict-free
    __shared__ __align__(16) float Wc[128 * 16];   // folded weights [e][h]
    __shared__ float kss[16], qss[16], badd[16];

    const int i  = blockIdx.x;
    const int b  = blockIdx.y;
    const int tid = threadIdx.x;

    // --- inline ksum/qsum: threads 0..127 -> ksum, 128..255 -> qsum ---
    {
        const float* src = (tid < 128) ? g_K : g_Q;
        const int t  = tid & 127;
        const int hh = t >> 3;
        const int d4 = t & 7;
        const float4 vv = *(const float4*)(src + ((size_t)(b * H_ + hh) * S_ + i) * DH_ + d4 * 4);
        float s = (vv.x + vv.y) + (vv.z + vv.w);
        s += __shfl_xor_sync(0xffffffffu, s, 1);
        s += __shfl_xor_sync(0xffffffffu, s, 2);
        s += __shfl_xor_sync(0xffffffffu, s, 4);
        if (d4 == 0) { if (tid < 128) kss[hh] = s; else qss[hh] = s; }
    }
    __syncthreads();

    // folded weights + bias (once per (b,i) row)
#pragma unroll
    for (int u = 0; u < 8; u++) {
        const int f = tid + u * 256;
        const int e = f >> 4;
        const int h = f & 15;
        Wc[f] = Wrqk[e * 32 + 2 * h] * kss[h] + Wrqk[e * 32 + 2 * h + 1] * qss[h];
    }
    if (tid < 16)
        badd[tid] = brqk[2 * tid] * kss[tid] + brqk[2 * tid + 1] * qss[tid];

    const float4* pg4 = (const float4*)(P + ((size_t)(b * S_ + i)) * S_ * E_);
    const int* mrow = mask + ((size_t)(b * S_ + i)) * S_;

    // stage chunk 0
    {
#pragma unroll
        for (int u = 0; u < 8; u++) {
            const int f4 = tid + u * 256;
            const float4 v = pg4[f4];
            const int j  = f4 >> 5;
            const int e0 = (f4 & 31) * 4;
            pT[(e0 + 0) * 65 + j] = v.x;
            pT[(e0 + 1) * 65 + j] = v.y;
            pT[(e0 + 2) * 65 + j] = v.z;
            pT[(e0 + 3) * 65 + j] = v.w;
        }
    }
    __syncthreads();

    const int jg = tid & 63;
    const int hg = tid >> 6;

    for (int c = 0; c < 8; c++) {
        const bool hasn = (c < 7);
        float4 pr[8];
        if (hasn) {
#pragma unroll
            for (int u = 0; u < 8; u++)
                pr[u] = pg4[(c + 1) * 2048 + tid + u * 256];
        }
        const int mv = mrow[c * 64 + jg];   // head-independent mask

        ull acc2[2];
        acc2[0] = 0ULL; acc2[1] = 0ULL;

#pragma unroll 4
        for (int e = 0; e < 128; e++) {
            const float pv = pT[e * 65 + jg];
            const ull pp = pack2(pv, pv);
            const ulonglong2 w01 = *(const ulonglong2*)(Wc + e * 16 + hg * 4);
            ffma2(acc2[0], pp, w01.x);
            ffma2(acc2[1], pp, w01.y);
        }

        const int jglob = c * 64 + jg;
#pragma unroll
        for (int k = 0; k < 2; k++) {
            const float2 v = unpack2(acc2[k]);
            const int h0 = hg * 4 + 2 * k;
            const int h1 = h0 + 1;
            const float o0 = (mv != 0) ? (v.x + badd[h0]) * SCALE_L2E : MASKED_SCORE;
            const float o1 = (mv != 0) ? (v.y + badd[h1]) * SCALE_L2E : MASKED_SCORE;
            g_RADD[((size_t)(b * H_ + h0) * S_ + i) * S_ + jglob] = o0;
            g_RADD[((size_t)(b * H_ + h1) * S_ + i) * S_ + jglob] = o1;
        }

        if (hasn) {
            __syncthreads();
#pragma unroll
            for (int u = 0; u < 8; u++) {
                const int f4 = tid + u * 256;
                const int j  = f4 >> 5;
                const int e0 = (f4 & 31) * 4;
                pT[(e0 + 0) * 65 + j] = pr[u].x;
                pT[(e0 + 1) * 65 + j] = pr[u].y;
                pT[(e0 + 2) * 65 + j] = pr[u].z;
                pT[(e0 + 3) * 65 + j] = pr[u].w;
            }
            __syncthreads();
        }
    }
}

// ---------------------------------------------------------------------------
// Kernel C: fused attention. Mask pre-folded into RADD -> no mask handling.
// 3 CTAs/SM via launch bounds; k prefetched in regs, v LDG'd at stage time.
// ---------------------------------------------------------------------------
__global__ void __launch_bounds__(256, 3) attn_kernel(float* __restrict__ out)
{
    __shared__ __align__(16) float q_s[32 * 68];   // [d][i], pre-scaled
    __shared__ __align__(16) float k_s[32 * 68];   // [d][j]
    __shared__ __align__(16) float v_s[32 * 68];   // [d][j]
    __shared__ __align__(16) float s_s[64 * 68];   // [i][j] probs

    const int b  = blockIdx.z;
    const int h  = blockIdx.y;
    const int i0 = blockIdx.x * 64;
    const int tid  = threadIdx.x;
    const int tx = tid & 15;
    const int ty = tid >> 4;

    const size_t bh = (size_t)(b * H_ + h);
    const float* kg_base = g_K + (bh * S_) * DH_;
    const float* vg_base = g_V + (bh * S_) * DH_;

    // load q tile transposed, pre-scaled
    {
        const float* qg = g_Q + (bh * S_ + i0) * DH_;
#pragma unroll
        for (int u = 0; u < 8; u++) {
            const int f = tid + u * 256;
            const int i = f >> 5;
            const int d = f & 31;
            q_s[d * 68 + i] = qg[f] * SCALE_L2E;
        }
    }

    // stage tile 0
    {
        const float4* kg4 = (const float4*)kg_base;
        const float4* vg4 = (const float4*)vg_base;
#pragma unroll
        for (int u = 0; u < 2; u++) {
            const int f4 = tid + u * 256;
            const int j  = f4 >> 3;
            const int d0 = (f4 & 7) * 4;
            const float4 kv = kg4[f4];
            const float4 vv = vg4[f4];
            k_s[(d0 + 0) * 68 + j] = kv.x;
            k_s[(d0 + 1) * 68 + j] = kv.y;
            k_s[(d0 + 2) * 68 + j] = kv.z;
            k_s[(d0 + 3) * 68 + j] = kv.w;
            v_s[(d0 + 0) * 68 + j] = vv.x;
            v_s[(d0 + 1) * 68 + j] = vv.y;
            v_s[(d0 + 2) * 68 + j] = vv.z;
            v_s[(d0 + 3) * 68 + j] = vv.w;
        }
    }
    __syncthreads();

    float m4[4], l4[4];
#pragma unroll
    for (int ii = 0; ii < 4; ii++) { m4[ii] = MASKED_SCORE; l4[ii] = 0.0f; }

    ull accJ[4][2];
#pragma unroll
    for (int a = 0; a < 4; a++) { accJ[a][0] = 0ULL; accJ[a][1] = 0ULL; }

    for (int t = 0; t < 8; t++) {
        const int j0 = t * 64;
        const bool hasn = (t < 7);

        // prefetch next k tile into registers (v loaded at stage time)
        float4 kr[2];
        if (hasn) {
            const float4* kg4 = (const float4*)(kg_base + (size_t)(j0 + 64) * DH_);
#pragma unroll
            for (int u = 0; u < 2; u++)
                kr[u] = kg4[tid + u * 256];
        }

        // prefetch RADD (mask already folded in)
        float4 r4[4];
#pragma unroll
        for (int ii = 0; ii < 4; ii++) {
            const int i = i0 + ty * 4 + ii;
            r4[ii] = *(const float4*)(g_RADD + (bh * S_ + i) * S_ + j0 + tx * 4);
        }

        // --- QK^T 64x64, FFMA2 pairs over j ---
        ull acc2[4][2];
#pragma unroll
        for (int a = 0; a < 4; a++) { acc2[a][0] = 0ULL; acc2[a][1] = 0ULL; }

#pragma unroll
        for (int d = 0; d < 32; d++) {
            float av[4];
            *(float4*)(av) = *(const float4*)(q_s + d * 68 + ty * 4);
            const ulonglong2 bq = *(const ulonglong2*)(k_s + d * 68 + tx * 4);
#pragma unroll
            for (int ii = 0; ii < 4; ii++) {
                const ull ap = pack2(av[ii], av[ii]);
                ffma2(acc2[ii][0], ap, bq.x);
                ffma2(acc2[ii][1], ap, bq.y);
            }
        }

        // --- softmax fully in registers (16-lane j-group reduction) ---
#pragma unroll
        for (int ii = 0; ii < 4; ii++) {
            const float2 p01 = unpack2(acc2[ii][0]);
            const float2 p23 = unpack2(acc2[ii][1]);
            const float x0 = p01.x + r4[ii].x;
            const float x1 = p01.y + r4[ii].y;
            const float x2 = p23.x + r4[ii].z;
            const float x3 = p23.y + r4[ii].w;

            float mx = fmaxf(fmaxf(x0, x1), fmaxf(x2, x3));
#pragma unroll
            for (int off = 8; off > 0; off >>= 1)
                mx = fmaxf(mx, __shfl_xor_sync(0xffffffffu, mx, off));

            const float m_new = fmaxf(m4[ii], mx);
            const float e0 = exp2f(x0 - m_new);
            const float e1 = exp2f(x1 - m_new);
            const float e2 = exp2f(x2 - m_new);
            const float e3 = exp2f(x3 - m_new);

            float sm = (e0 + e1) + (e2 + e3);
#pragma unroll
            for (int off = 8; off > 0; off >>= 1)
                sm += __shfl_xor_sync(0xffffffffu, sm, off);

            const float alpha = exp2f(m4[ii] - m_new);
            l4[ii] = l4[ii] * alpha + sm;
            m4[ii] = m_new;

            const ull ap = pack2(alpha, alpha);
            accJ[ii][0] = fmul2(accJ[ii][0], ap);
            accJ[ii][1] = fmul2(accJ[ii][1], ap);

            *(float4*)(s_s + (ty * 4 + ii) * 68 + tx * 4) = make_float4(e0, e1, e2, e3);
        }
        __syncthreads();   // probs visible

        // --- PV: thread = 4i x 2d, FFMA2 packed over (even j, odd j) ---
        const int ib = ty * 4;
        const int d0 = tx * 2;
#pragma unroll 4
        for (int j4 = 0; j4 < 64; j4 += 4) {
            const ulonglong2 v0 = *(const ulonglong2*)(v_s + (d0 + 0) * 68 + j4);
            const ulonglong2 v1 = *(const ulonglong2*)(v_s + (d0 + 1) * 68 + j4);
#pragma unroll
            for (int ii = 0; ii < 4; ii++) {
                const ulonglong2 pp = *(const ulonglong2*)(s_s + (ib + ii) * 68 + j4);
                ffma2(accJ[ii][0], pp.x, v0.x);
                ffma2(accJ[ii][0], pp.y, v0.y);
                ffma2(accJ[ii][1], pp.x, v1.x);
                ffma2(accJ[ii][1], pp.y, v1.y);
            }
        }

        if (hasn) {
            __syncthreads();   // all reads of k_s/v_s/s_s done
            const float4* vg4 = (const float4*)(vg_base + (size_t)(j0 + 64) * DH_);
#pragma unroll
            for (int u = 0; u < 2; u++) {
                const int f4 = tid + u * 256;
                const int j  = f4 >> 3;
                const int dd = (f4 & 7) * 4;
                const float4 vv = vg4[f4];   // fresh LDG, covered by other warps
                k_s[(dd + 0) * 68 + j] = kr[u].x;
                k_s[(dd + 1) * 68 + j] = kr[u].y;
                k_s[(dd + 2) * 68 + j] = kr[u].z;
                k_s[(dd + 3) * 68 + j] = kr[u].w;
                v_s[(dd + 0) * 68 + j] = vv.x;
                v_s[(dd + 1) * 68 + j] = vv.y;
                v_s[(dd + 2) * 68 + j] = vv.z;
                v_s[(dd + 3) * 68 + j] = vv.w;
            }
            __syncthreads();   // new tile visible
        }
    }

    // epilogue
    const int ib = ty * 4;
    const int d0 = tx * 2;
#pragma unroll
    for (int ii = 0; ii < 4; ii++) {
        const float inv = 1.0f / l4[ii];
        const float2 o0 = unpack2(accJ[ii][0]);
        const float2 o1 = unpack2(accJ[ii][1]);
        float2 res;
        res.x = (o0.x + o0.y) * inv;
        res.y = (o1.x + o1.y) * inv;
        *(float2*)(out + ((size_t)(b * S_ + i0 + ib + ii)) * D_ + h * DH_ + d0) = res;
    }
}

// ---------------------------------------------------------------------------
extern "C" void kernel_launch(void* const* d_in, const int* in_sizes, int n_in,
                              void* d_out, int out_size)
{
    const float* x     = (const float*)d_in[0];
    const float* p     = (const float*)d_in[1];
    const int*   mask  = (const int*)  d_in[2];
    const float* Wqkv  = (const float*)d_in[3];
    const float* bqkv  = (const float*)d_in[4];
    const float* Wrqk  = (const float*)d_in[5];
    const float* brqk  = (const float*)d_in[6];
    float* out = (float*)d_out;

    (void)in_sizes; (void)n_in; (void)out_size;

    qkv_gemm_kernel<<<dim3(1536 / 128, 2048 / 128), 256>>>(x, Wqkv, bqkv);
    radd_kernel<<<dim3(S_, B_), 256>>>(p, Wrqk, brqk, mask);
    attn_kernel<<<dim3(S_ / 64, H_, B_), 256>>>(out);
}

// round 14
// speedup vs baseline: 1.0979x; 1.0615x over previous
#include <cuda_runtime.h>
#include <cuda_bf16.h>

#define B_  4
#define S_  512
#define D_  512
#define H_  16
#define DH_ 32
#define E_  128

typedef unsigned long long ull;

// ---- f32x2 packed-math helpers (sm_103a FFMA2 path, PTX-only) -------------
__device__ __forceinline__ ull pack2(float x, float y) {
    ull r; asm("mov.b64 %0, {%1, %2};" : "=l"(r) : "f"(x), "f"(y)); return r;
}
__device__ __forceinline__ void ffma2(ull& d, ull a, ull b) {
    asm("fma.rn.f32x2 %0, %1, %2, %0;" : "+l"(d) : "l"(a), "l"(b));
}
__device__ __forceinline__ ull fmul2(ull a, ull b) {
    ull r; asm("mul.rn.f32x2 %0, %1, %2;" : "=l"(r) : "l"(a), "l"(b)); return r;
}
__device__ __forceinline__ float2 unpack2(ull v) {
    float2 f; asm("mov.b64 {%0, %1}, %2;" : "=f"(f.x), "=f"(f.y) : "l"(v)); return f;
}

// scale * log2(e): scores pre-multiplied so softmax uses exp2f directly.
#define SCALE_L2E (0.10206207261596576f * 1.4426950408889634f)
#define MASKED_SCORE (-1e30f)

// fp32 scratch (static device globals; no allocation anywhere)
__device__ float g_Q[B_*H_*S_*DH_];
__device__ float g_K[B_*H_*S_*DH_];
__device__ float g_V[B_*H_*S_*DH_];
__device__ float g_P0[2048 * 1536];     // split-K partial 0
__device__ float g_P1[2048 * 1536];     // split-K partial 1
__device__ float g_RADD[B_*H_*S_*S_];   // folded edge term * SCALE_L2E, mask folded in

// ---------------------------------------------------------------------------
// Kernel A: split-K qkv GEMM. blockIdx.z selects K half (256 each).
// 128x128 tile, 8x8 microtile, FFMA2, double-buffered smem.
// Coalesced float4 stores into per-half partial buffers (no scatter here).
// ---------------------------------------------------------------------------
__global__ void __launch_bounds__(256) qkv_gemm_kernel(
    const float* __restrict__ X, const float* __restrict__ W)
{
    __shared__ __align__(16) float As[2][8 * 132];
    __shared__ __align__(16) float Bs[2][8 * 128];

    const int m0 = blockIdx.y * 128;
    const int n0 = blockIdx.x * 128;
    const int ks = blockIdx.z * 256;
    float* __restrict__ Pout = blockIdx.z ? g_P1 : g_P0;

    const int tid = threadIdx.x;
    const int tx = tid & 15;
    const int ty = tid >> 4;

    const int lm  = tid >> 1;
    const int lkq = (tid & 1) * 4;
    const int lkr = tid >> 5;
    const int lnq = (tid & 31) * 4;

    const float* Ag = X + (size_t)(m0 + lm) * 512 + ks + lkq;
    const float* Bg = W + (size_t)(ks + lkr) * 1536 + n0 + lnq;

    ull acc2[8][4];
#pragma unroll
    for (int i = 0; i < 8; i++)
#pragma unroll
        for (int j = 0; j < 4; j++) acc2[i][j] = 0ULL;

    {
        float4 av = *(const float4*)(Ag);
        float4 bv = *(const float4*)(Bg);
        As[0][(lkq + 0) * 132 + lm] = av.x;
        As[0][(lkq + 1) * 132 + lm] = av.y;
        As[0][(lkq + 2) * 132 + lm] = av.z;
        As[0][(lkq + 3) * 132 + lm] = av.w;
        *(float4*)(&Bs[0][lkr * 128 + lnq]) = bv;
    }
    __syncthreads();

    int buf = 0;
    for (int k0 = 0; k0 < 256; k0 += 8) {
        const bool has_next = (k0 + 8) < 256;
        float4 av, bv;
        if (has_next) {
            av = *(const float4*)(Ag + k0 + 8);
            bv = *(const float4*)(Bg + (size_t)(k0 + 8) * 1536);
        }

        const float* Asb = As[buf];
        const float* Bsb = Bs[buf];
#pragma unroll
        for (int kk = 0; kk < 8; kk++) {
            float a[8];
            *(float4*)(a)     = *(const float4*)(Asb + kk * 132 + ty * 8);
            *(float4*)(a + 4) = *(const float4*)(Asb + kk * 132 + ty * 8 + 4);
            ulonglong2 b01 = *(const ulonglong2*)(Bsb + kk * 128 + tx * 8);
            ulonglong2 b23 = *(const ulonglong2*)(Bsb + kk * 128 + tx * 8 + 4);
            ull bp0 = b01.x, bp1 = b01.y, bp2 = b23.x, bp3 = b23.y;
#pragma unroll
            for (int i = 0; i < 8; i++) {
                const ull ap = pack2(a[i], a[i]);
                ffma2(acc2[i][0], ap, bp0);
                ffma2(acc2[i][1], ap, bp1);
                ffma2(acc2[i][2], ap, bp2);
                ffma2(acc2[i][3], ap, bp3);
            }
        }

        if (has_next) {
            const int nb = buf ^ 1;
            As[nb][(lkq + 0) * 132 + lm] = av.x;
            As[nb][(lkq + 1) * 132 + lm] = av.y;
            As[nb][(lkq + 2) * 132 + lm] = av.z;
            As[nb][(lkq + 3) * 132 + lm] = av.w;
            *(float4*)(&Bs[nb][lkr * 128 + lnq]) = bv;
            __syncthreads();
            buf = nb;
        }
    }

    // coalesced epilogue into partial buffer [m][n]
#pragma unroll
    for (int i = 0; i < 8; i++) {
        const int m = m0 + ty * 8 + i;
        float* dst = Pout + (size_t)m * 1536 + n0 + tx * 8;
        const float2 v0 = unpack2(acc2[i][0]);
        const float2 v1 = unpack2(acc2[i][1]);
        const float2 v2 = unpack2(acc2[i][2]);
        const float2 v3 = unpack2(acc2[i][3]);
        *(float4*)(dst)     = make_float4(v0.x, v0.y, v1.x, v1.y);
        *(float4*)(dst + 4) = make_float4(v2.x, v2.y, v3.x, v3.y);
    }
}

// ---------------------------------------------------------------------------
// Kernel A2: combine split-K partials + bias, scatter to Q/K/V [B,H,S,dh].
// ---------------------------------------------------------------------------
__global__ void __launch_bounds__(256) qkv_combine_kernel(
    const float* __restrict__ bias)
{
    const int idx = blockIdx.x * 256 + threadIdx.x;     // float4 index
    const float4 a = ((const float4*)g_P0)[idx];
    const float4 b = ((const float4*)g_P1)[idx];
    const int m  = idx / 384;          // 1536/4
    const int n  = (idx - m * 384) * 4;
    const float4 bs = *(const float4*)(bias + n);

    const int bb = m >> 9;
    const int s  = m & 511;
    const int h  = n / 96;
    const int r  = n - h * 96;
    const int t3 = r >> 5;             // constant across the 4 lanes (r%4==0, r%32<=28)
    const int d  = r & 31;
    float* dst = (t3 == 0) ? g_Q : ((t3 == 1) ? g_K : g_V);
    *(float4*)(dst + ((size_t)(bb * H_ + h) * S_ + s) * DH_ + d) =
        make_float4(a.x + b.x + bs.x, a.y + b.y + bs.y,
                    a.z + b.z + bs.z, a.w + b.w + bs.w);
}

// ---------------------------------------------------------------------------
// Kernel B: folded edge projection, mask folded in, sums fused inline.
// CTA = (b, i), 256 threads, 8 chunks of 64 j. Register-prefetch pipeline.
// ---------------------------------------------------------------------------
__global__ void __launch_bounds__(256) radd_kernel(
    const float* __restrict__ P, const float* __restrict__ Wrqk,
    const float* __restrict__ brqk, const int* __restrict__ mask)
{
    __shared__ __align__(16) float pT[128 * 65];   // [e][j], conflict-free
    __shared__ __align__(16) float Wc[128 * 16];   // folded weights [e][h]
    __shared__ float kss[16], qss[16], badd[16];

    const int i  = blockIdx.x;
    const int b  = blockIdx.y;
    const int tid = threadIdx.x;

    // --- inline ksum/qsum: threads 0..127 -> ksum, 128..255 -> qsum ---
    {
        const float* src = (tid < 128) ? g_K : g_Q;
        const int t  = tid & 127;
        const int hh = t >> 3;
        const int d4 = t & 7;
        const float4 vv = *(const float4*)(src + ((size_t)(b * H_ + hh) * S_ + i) * DH_ + d4 * 4);
        float s = (vv.x + vv.y) + (vv.z + vv.w);
        s += __shfl_xor_sync(0xffffffffu, s, 1);
        s += __shfl_xor_sync(0xffffffffu, s, 2);
        s += __shfl_xor_sync(0xffffffffu, s, 4);
        if (d4 == 0) { if (tid < 128) kss[hh] = s; else qss[hh] = s; }
    }
    __syncthreads();

    // folded weights + bias (once per (b,i) row)
#pragma unroll
    for (int u = 0; u < 8; u++) {
        const int f = tid + u * 256;
        const int e = f >> 4;
        const int h = f & 15;
        Wc[f] = Wrqk[e * 32 + 2 * h] * kss[h] + Wrqk[e * 32 + 2 * h + 1] * qss[h];
    }
    if (tid < 16)
        badd[tid] = brqk[2 * tid] * kss[tid] + brqk[2 * tid + 1] * qss[tid];

    const float4* pg4 = (const float4*)(P + ((size_t)(b * S_ + i)) * S_ * E_);
    const int* mrow = mask + ((size_t)(b * S_ + i)) * S_;

    // stage chunk 0
    {
#pragma unroll
        for (int u = 0; u < 8; u++) {
            const int f4 = tid + u * 256;
            const float4 v = pg4[f4];
            const int j  = f4 >> 5;
            const int e0 = (f4 & 31) * 4;
            pT[(e0 + 0) * 65 + j] = v.x;
            pT[(e0 + 1) * 65 + j] = v.y;
            pT[(e0 + 2) * 65 + j] = v.z;
            pT[(e0 + 3) * 65 + j] = v.w;
        }
    }
    __syncthreads();

    const int jg = tid & 63;
    const int hg = tid >> 6;

    for (int c = 0; c < 8; c++) {
        const bool hasn = (c < 7);
        float4 pr[8];
        if (hasn) {
#pragma unroll
            for (int u = 0; u < 8; u++)
                pr[u] = pg4[(c + 1) * 2048 + tid + u * 256];
        }
        const int mv = mrow[c * 64 + jg];   // head-independent mask

        ull acc2[2];
        acc2[0] = 0ULL; acc2[1] = 0ULL;

#pragma unroll 4
        for (int e = 0; e < 128; e++) {
            const float pv = pT[e * 65 + jg];
            const ull pp = pack2(pv, pv);
            const ulonglong2 w01 = *(const ulonglong2*)(Wc + e * 16 + hg * 4);
            ffma2(acc2[0], pp, w01.x);
            ffma2(acc2[1], pp, w01.y);
        }

        const int jglob = c * 64 + jg;
#pragma unroll
        for (int k = 0; k < 2; k++) {
            const float2 v = unpack2(acc2[k]);
            const int h0 = hg * 4 + 2 * k;
            const int h1 = h0 + 1;
            const float o0 = (mv != 0) ? (v.x + badd[h0]) * SCALE_L2E : MASKED_SCORE;
            const float o1 = (mv != 0) ? (v.y + badd[h1]) * SCALE_L2E : MASKED_SCORE;
            g_RADD[((size_t)(b * H_ + h0) * S_ + i) * S_ + jglob] = o0;
            g_RADD[((size_t)(b * H_ + h1) * S_ + i) * S_ + jglob] = o1;
        }

        if (hasn) {
            __syncthreads();
#pragma unroll
            for (int u = 0; u < 8; u++) {
                const int f4 = tid + u * 256;
                const int j  = f4 >> 5;
                const int e0 = (f4 & 31) * 4;
                pT[(e0 + 0) * 65 + j] = pr[u].x;
                pT[(e0 + 1) * 65 + j] = pr[u].y;
                pT[(e0 + 2) * 65 + j] = pr[u].z;
                pT[(e0 + 3) * 65 + j] = pr[u].w;
            }
            __syncthreads();
        }
    }
}

// ---------------------------------------------------------------------------
// Kernel C: fused attention. Mask pre-folded into RADD -> no mask handling.
// ---------------------------------------------------------------------------
__global__ void __launch_bounds__(256, 3) attn_kernel(float* __restrict__ out)
{
    __shared__ __align__(16) float q_s[32 * 68];   // [d][i], pre-scaled
    __shared__ __align__(16) float k_s[32 * 68];   // [d][j]
    __shared__ __align__(16) float v_s[32 * 68];   // [d][j]
    __shared__ __align__(16) float s_s[64 * 68];   // [i][j] probs

    const int b  = blockIdx.z;
    const int h  = blockIdx.y;
    const int i0 = blockIdx.x * 64;
    const int tid  = threadIdx.x;
    const int tx = tid & 15;
    const int ty = tid >> 4;

    const size_t bh = (size_t)(b * H_ + h);
    const float* kg_base = g_K + (bh * S_) * DH_;
    const float* vg_base = g_V + (bh * S_) * DH_;

    // load q tile transposed, pre-scaled
    {
        const float* qg = g_Q + (bh * S_ + i0) * DH_;
#pragma unroll
        for (int u = 0; u < 8; u++) {
            const int f = tid + u * 256;
            const int i = f >> 5;
            const int d = f & 31;
            q_s[d * 68 + i] = qg[f] * SCALE_L2E;
        }
    }

    // stage tile 0
    {
        const float4* kg4 = (const float4*)kg_base;
        const float4* vg4 = (const float4*)vg_base;
#pragma unroll
        for (int u = 0; u < 2; u++) {
            const int f4 = tid + u * 256;
            const int j  = f4 >> 3;
            const int d0 = (f4 & 7) * 4;
            const float4 kv = kg4[f4];
            const float4 vv = vg4[f4];
            k_s[(d0 + 0) * 68 + j] = kv.x;
            k_s[(d0 + 1) * 68 + j] = kv.y;
            k_s[(d0 + 2) * 68 + j] = kv.z;
            k_s[(d0 + 3) * 68 + j] = kv.w;
            v_s[(d0 + 0) * 68 + j] = vv.x;
            v_s[(d0 + 1) * 68 + j] = vv.y;
            v_s[(d0 + 2) * 68 + j] = vv.z;
            v_s[(d0 + 3) * 68 + j] = vv.w;
        }
    }
    __syncthreads();

    float m4[4], l4[4];
#pragma unroll
    for (int ii = 0; ii < 4; ii++) { m4[ii] = MASKED_SCORE; l4[ii] = 0.0f; }

    ull accJ[4][2];
#pragma unroll
    for (int a = 0; a < 4; a++) { accJ[a][0] = 0ULL; accJ[a][1] = 0ULL; }

    for (int t = 0; t < 8; t++) {
        const int j0 = t * 64;
        const bool hasn = (t < 7);

        // prefetch next k tile into registers (v loaded at stage time)
        float4 kr[2];
        if (hasn) {
            const float4* kg4 = (const float4*)(kg_base + (size_t)(j0 + 64) * DH_);
#pragma unroll
            for (int u = 0; u < 2; u++)
                kr[u] = kg4[tid + u * 256];
        }

        // prefetch RADD (mask already folded in)
        float4 r4[4];
#pragma unroll
        for (int ii = 0; ii < 4; ii++) {
            const int i = i0 + ty * 4 + ii;
            r4[ii] = *(const float4*)(g_RADD + (bh * S_ + i) * S_ + j0 + tx * 4);
        }

        // --- QK^T 64x64, FFMA2 pairs over j ---
        ull acc2[4][2];
#pragma unroll
        for (int a = 0; a < 4; a++) { acc2[a][0] = 0ULL; acc2[a][1] = 0ULL; }

#pragma unroll
        for (int d = 0; d < 32; d++) {
            float av[4];
            *(float4*)(av) = *(const float4*)(q_s + d * 68 + ty * 4);
            const ulonglong2 bq = *(const ulonglong2*)(k_s + d * 68 + tx * 4);
#pragma unroll
            for (int ii = 0; ii < 4; ii++) {
                const ull ap = pack2(av[ii], av[ii]);
                ffma2(acc2[ii][0], ap, bq.x);
                ffma2(acc2[ii][1], ap, bq.y);
            }
        }

        // --- softmax fully in registers (16-lane j-group reduction) ---
#pragma unroll
        for (int ii = 0; ii < 4; ii++) {
            const float2 p01 = unpack2(acc2[ii][0]);
            const float2 p23 = unpack2(acc2[ii][1]);
            const float x0 = p01.x + r4[ii].x;
            const float x1 = p01.y + r4[ii].y;
            const float x2 = p23.x + r4[ii].z;
            const float x3 = p23.y + r4[ii].w;

            float mx = fmaxf(fmaxf(x0, x1), fmaxf(x2, x3));
#pragma unroll
            for (int off = 8; off > 0; off >>= 1)
                mx = fmaxf(mx, __shfl_xor_sync(0xffffffffu, mx, off));

            const float m_new = fmaxf(m4[ii], mx);
            const float e0 = exp2f(x0 - m_new);
            const float e1 = exp2f(x1 - m_new);
            const float e2 = exp2f(x2 - m_new);
            const float e3 = exp2f(x3 - m_new);

            float sm = (e0 + e1) + (e2 + e3);
#pragma unroll
            for (int off = 8; off > 0; off >>= 1)
                sm += __shfl_xor_sync(0xffffffffu, sm, off);

            const float alpha = exp2f(m4[ii] - m_new);
            l4[ii] = l4[ii] * alpha + sm;
            m4[ii] = m_new;

            const ull ap = pack2(alpha, alpha);
            accJ[ii][0] = fmul2(accJ[ii][0], ap);
            accJ[ii][1] = fmul2(accJ[ii][1], ap);

            *(float4*)(s_s + (ty * 4 + ii) * 68 + tx * 4) = make_float4(e0, e1, e2, e3);
        }
        __syncthreads();   // probs visible

        // --- PV: thread = 4i x 2d, FFMA2 packed over (even j, odd j) ---
        const int ib = ty * 4;
        const int d0 = tx * 2;
#pragma unroll 4
        for (int j4 = 0; j4 < 64; j4 += 4) {
            const ulonglong2 v0 = *(const ulonglong2*)(v_s + (d0 + 0) * 68 + j4);
            const ulonglong2 v1 = *(const ulonglong2*)(v_s + (d0 + 1) * 68 + j4);
#pragma unroll
            for (int ii = 0; ii < 4; ii++) {
                const ulonglong2 pp = *(const ulonglong2*)(s_s + (ib + ii) * 68 + j4);
                ffma2(accJ[ii][0], pp.x, v0.x);
                ffma2(accJ[ii][0], pp.y, v0.y);
                ffma2(accJ[ii][1], pp.x, v1.x);
                ffma2(accJ[ii][1], pp.y, v1.y);
            }
        }

        if (hasn) {
            __syncthreads();   // all reads of k_s/v_s/s_s done
            const float4* vg4 = (const float4*)(vg_base + (size_t)(j0 + 64) * DH_);
#pragma unroll
            for (int u = 0; u < 2; u++) {
                const int f4 = tid + u * 256;
                const int j  = f4 >> 3;
                const int dd = (f4 & 7) * 4;
                const float4 vv = vg4[f4];   // fresh LDG, covered by other warps
                k_s[(dd + 0) * 68 + j] = kr[u].x;
                k_s[(dd + 1) * 68 + j] = kr[u].y;
                k_s[(dd + 2) * 68 + j] = kr[u].z;
                k_s[(dd + 3) * 68 + j] = kr[u].w;
                v_s[(dd + 0) * 68 + j] = vv.x;
                v_s[(dd + 1) * 68 + j] = vv.y;
                v_s[(dd + 2) * 68 + j] = vv.z;
                v_s[(dd + 3) * 68 + j] = vv.w;
            }
            __syncthreads();   // new tile visible
        }
    }

    // epilogue
    const int ib = ty * 4;
    const int d0 = tx * 2;
#pragma unroll
    for (int ii = 0; ii < 4; ii++) {
        const float inv = 1.0f / l4[ii];
        const float2 o0 = unpack2(accJ[ii][0]);
        const float2 o1 = unpack2(accJ[ii][1]);
        float2 res;
        res.x = (o0.x + o0.y) * inv;
        res.y = (o1.x + o1.y) * inv;
        *(float2*)(out + ((size_t)(b * S_ + i0 + ib + ii)) * D_ + h * DH_ + d0) = res;
    }
}

// ---------------------------------------------------------------------------
extern "C" void kernel_launch(void* const* d_in, const int* in_sizes, int n_in,
                              void* d_out, int out_size)
{
    const float* x     = (const float*)d_in[0];
    const float* p     = (const float*)d_in[1];
    const int*   mask  = (const int*)  d_in[2];
    const float* Wqkv  = (const float*)d_in[3];
    const float* bqkv  = (const float*)d_in[4];
    const float* Wrqk  = (const float*)d_in[5];
    const float* brqk  = (const float*)d_in[6];
    float* out = (float*)d_out;

    (void)in_sizes; (void)n_in; (void)out_size;

    qkv_gemm_kernel<<<dim3(1536 / 128, 2048 / 128, 2), 256>>>(x, Wqkv);
    qkv_combine_kernel<<<(2048 * 1536 / 4) / 256, 256>>>(bqkv);
    radd_kernel<<<dim3(S_, B_), 256>>>(p, Wrqk, brqk, mask);
    attn_kernel<<<dim3(S_ / 64, H_, B_), 256>>>(out);
}

// round 15
// speedup vs baseline: 1.4985x; 1.3648x over previous
#include <cuda_runtime.h>
#include <cuda_bf16.h>

#define B_  4
#define S_  512
#define D_  512
#define H_  16
#define DH_ 32
#define E_  128

typedef unsigned long long ull;

// ---- f32x2 packed-math helpers (sm_103a FFMA2 path, PTX-only) -------------
__device__ __forceinline__ ull pack2(float x, float y) {
    ull r; asm("mov.b64 %0, {%1, %2};" : "=l"(r) : "f"(x), "f"(y)); return r;
}
__device__ __forceinline__ void ffma2(ull& d, ull a, ull b) {
    asm("fma.rn.f32x2 %0, %1, %2, %0;" : "+l"(d) : "l"(a), "l"(b));
}
__device__ __forceinline__ ull fmul2(ull a, ull b) {
    ull r; asm("mul.rn.f32x2 %0, %1, %2;" : "=l"(r) : "l"(a), "l"(b)); return r;
}
__device__ __forceinline__ float2 unpack2(ull v) {
    float2 f; asm("mov.b64 {%0, %1}, %2;" : "=f"(f.x), "=f"(f.y) : "l"(v)); return f;
}

// scale * log2(e): scores pre-multiplied so softmax uses exp2f directly.
#define SCALE_L2E (0.10206207261596576f * 1.4426950408889634f)
#define MASKED_SCORE (-1e30f)

// fp32 scratch (static device globals; no allocation anywhere)
__device__ float g_Q[B_*H_*S_*DH_];
__device__ float g_K[B_*H_*S_*DH_];
__device__ float g_V[B_*H_*S_*DH_];
__device__ float g_P0[2048 * 1536];     // split-K partial 0
__device__ float g_P1[2048 * 1536];     // split-K partial 1
__device__ float g_RADD[B_*H_*S_*S_];   // folded edge term * SCALE_L2E, mask folded in

// ---------------------------------------------------------------------------
// Kernel A: split-K qkv GEMM (unchanged from R14).
// ---------------------------------------------------------------------------
__global__ void __launch_bounds__(256) qkv_gemm_kernel(
    const float* __restrict__ X, const float* __restrict__ W)
{
    __shared__ __align__(16) float As[2][8 * 132];
    __shared__ __align__(16) float Bs[2][8 * 128];

    const int m0 = blockIdx.y * 128;
    const int n0 = blockIdx.x * 128;
    const int ks = blockIdx.z * 256;
    float* __restrict__ Pout = blockIdx.z ? g_P1 : g_P0;

    const int tid = threadIdx.x;
    const int tx = tid & 15;
    const int ty = tid >> 4;

    const int lm  = tid >> 1;
    const int lkq = (tid & 1) * 4;
    const int lkr = tid >> 5;
    const int lnq = (tid & 31) * 4;

    const float* Ag = X + (size_t)(m0 + lm) * 512 + ks + lkq;
    const float* Bg = W + (size_t)(ks + lkr) * 1536 + n0 + lnq;

    ull acc2[8][4];
#pragma unroll
    for (int i = 0; i < 8; i++)
#pragma unroll
        for (int j = 0; j < 4; j++) acc2[i][j] = 0ULL;

    {
        float4 av = *(const float4*)(Ag);
        float4 bv = *(const float4*)(Bg);
        As[0][(lkq + 0) * 132 + lm] = av.x;
        As[0][(lkq + 1) * 132 + lm] = av.y;
        As[0][(lkq + 2) * 132 + lm] = av.z;
        As[0][(lkq + 3) * 132 + lm] = av.w;
        *(float4*)(&Bs[0][lkr * 128 + lnq]) = bv;
    }
    __syncthreads();

    int buf = 0;
    for (int k0 = 0; k0 < 256; k0 += 8) {
        const bool has_next = (k0 + 8) < 256;
        float4 av, bv;
        if (has_next) {
            av = *(const float4*)(Ag + k0 + 8);
            bv = *(const float4*)(Bg + (size_t)(k0 + 8) * 1536);
        }

        const float* Asb = As[buf];
        const float* Bsb = Bs[buf];
#pragma unroll
        for (int kk = 0; kk < 8; kk++) {
            float a[8];
            *(float4*)(a)     = *(const float4*)(Asb + kk * 132 + ty * 8);
            *(float4*)(a + 4) = *(const float4*)(Asb + kk * 132 + ty * 8 + 4);
            ulonglong2 b01 = *(const ulonglong2*)(Bsb + kk * 128 + tx * 8);
            ulonglong2 b23 = *(const ulonglong2*)(Bsb + kk * 128 + tx * 8 + 4);
            ull bp0 = b01.x, bp1 = b01.y, bp2 = b23.x, bp3 = b23.y;
#pragma unroll
            for (int i = 0; i < 8; i++) {
                const ull ap = pack2(a[i], a[i]);
                ffma2(acc2[i][0], ap, bp0);
                ffma2(acc2[i][1], ap, bp1);
                ffma2(acc2[i][2], ap, bp2);
                ffma2(acc2[i][3], ap, bp3);
            }
        }

        if (has_next) {
            const int nb = buf ^ 1;
            As[nb][(lkq + 0) * 132 + lm] = av.x;
            As[nb][(lkq + 1) * 132 + lm] = av.y;
            As[nb][(lkq + 2) * 132 + lm] = av.z;
            As[nb][(lkq + 3) * 132 + lm] = av.w;
            *(float4*)(&Bs[nb][lkr * 128 + lnq]) = bv;
            __syncthreads();
            buf = nb;
        }
    }

#pragma unroll
    for (int i = 0; i < 8; i++) {
        const int m = m0 + ty * 8 + i;
        float* dst = Pout + (size_t)m * 1536 + n0 + tx * 8;
        const float2 v0 = unpack2(acc2[i][0]);
        const float2 v1 = unpack2(acc2[i][1]);
        const float2 v2 = unpack2(acc2[i][2]);
        const float2 v3 = unpack2(acc2[i][3]);
        *(float4*)(dst)     = make_float4(v0.x, v0.y, v1.x, v1.y);
        *(float4*)(dst + 4) = make_float4(v2.x, v2.y, v3.x, v3.y);
    }
}

// ---------------------------------------------------------------------------
// Kernel A2: combine split-K partials + bias, scatter to Q/K/V.
// ---------------------------------------------------------------------------
__global__ void __launch_bounds__(256) qkv_combine_kernel(
    const float* __restrict__ bias)
{
    const int idx = blockIdx.x * 256 + threadIdx.x;     // float4 index
    const float4 a = ((const float4*)g_P0)[idx];
    const float4 b = ((const float4*)g_P1)[idx];
    const int m  = idx / 384;          // 1536/4
    const int n  = (idx - m * 384) * 4;
    const float4 bs = *(const float4*)(bias + n);

    const int bb = m >> 9;
    const int s  = m & 511;
    const int h  = n / 96;
    const int r  = n - h * 96;
    const int t3 = r >> 5;
    const int d  = r & 31;
    float* dst = (t3 == 0) ? g_Q : ((t3 == 1) ? g_K : g_V);
    *(float4*)(dst + ((size_t)(bb * H_ + h) * S_ + s) * DH_ + d) =
        make_float4(a.x + b.x + bs.x, a.y + b.y + bs.y,
                    a.z + b.z + bs.z, a.w + b.w + bs.w);
}

// ---------------------------------------------------------------------------
// Kernel B (REWRITTEN): folded edge projection, 2j x 8h microtile.
// CTA = (b,i), 256 threads = 128 j-pair groups x 2 head-groups.
// j-chunks of 256 (2 per row); e-blocks of 32 staged in swizzled transposed
// tile pT[32e][260] (col = j ^ ((e>>2)<<2) -> conflict-free STS and LDS.64).
// Per e per warp: 2 wf (pT) + 2 wf (Wc bcast) per 512 MACs = 128 MACs/wf.
// LDG prefetch pipelined across e-blocks. Mask folded into output.
// ---------------------------------------------------------------------------
__global__ void __launch_bounds__(256) radd_kernel(
    const float* __restrict__ P, const float* __restrict__ Wrqk,
    const float* __restrict__ brqk, const int* __restrict__ mask)
{
    __shared__ __align__(16) float pT[32 * 260];   // 33.3 KB, swizzled [e][j']
    __shared__ __align__(16) float Wc[128 * 16];   // folded weights [e][h]
    __shared__ float kss[16], qss[16], badd[16];

    const int i  = blockIdx.x;
    const int b  = blockIdx.y;
    const int tid = threadIdx.x;

    // --- inline ksum/qsum: threads 0..127 -> ksum, 128..255 -> qsum ---
    {
        const float* src = (tid < 128) ? g_K : g_Q;
        const int t  = tid & 127;
        const int hh = t >> 3;
        const int d4 = t & 7;
        const float4 vv = *(const float4*)(src + ((size_t)(b * H_ + hh) * S_ + i) * DH_ + d4 * 4);
        float s = (vv.x + vv.y) + (vv.z + vv.w);
        s += __shfl_xor_sync(0xffffffffu, s, 1);
        s += __shfl_xor_sync(0xffffffffu, s, 2);
        s += __shfl_xor_sync(0xffffffffu, s, 4);
        if (d4 == 0) { if (tid < 128) kss[hh] = s; else qss[hh] = s; }
    }
    __syncthreads();

    // folded weights + bias (once per (b,i) row)
#pragma unroll
    for (int u = 0; u < 8; u++) {
        const int f = tid + u * 256;
        const int e = f >> 4;
        const int h = f & 15;
        Wc[f] = Wrqk[e * 32 + 2 * h] * kss[h] + Wrqk[e * 32 + 2 * h + 1] * qss[h];
    }
    if (tid < 16)
        badd[tid] = brqk[2 * tid] * kss[tid] + brqk[2 * tid + 1] * qss[tid];

    const float4* pg4 = (const float4*)(P + ((size_t)(b * S_ + i)) * S_ * E_);
    const int* mrow = mask + ((size_t)(b * S_ + i)) * S_;

    const int jg = tid & 127;     // j-pair group (j = 2jg, 2jg+1 within chunk)
    const int hg = tid >> 7;      // 0/1 -> heads hg*8 .. hg*8+7
    const int j2 = jg * 2;

    // prefetch block (c=0, eb=0): idx -> j_local = idx>>3, e4 = idx&7
    float4 pr[8];
#pragma unroll
    for (int u = 0; u < 8; u++) {
        const int idx = tid + u * 256;
        pr[u] = pg4[(size_t)(idx >> 3) * 32 + (idx & 7)];
    }

    for (int c = 0; c < 2; c++) {
        ull acc2[2][4];
#pragma unroll
        for (int a = 0; a < 2; a++)
#pragma unroll
            for (int q = 0; q < 4; q++) acc2[a][q] = 0ULL;

        for (int eb = 0; eb < 4; eb++) {
            __syncthreads();   // pT free (also orders Wc/kss on first pass)

            // transpose-store prefetched block into swizzled pT
#pragma unroll
            for (int u = 0; u < 8; u++) {
                const int idx = tid + u * 256;
                const int jl  = idx >> 3;        // 0..255
                const int e4  = idx & 7;         // 0..7
                const int col = jl ^ (e4 << 2);  // swizzle
                pT[(e4 * 4 + 0) * 260 + col] = pr[u].x;
                pT[(e4 * 4 + 1) * 260 + col] = pr[u].y;
                pT[(e4 * 4 + 2) * 260 + col] = pr[u].z;
                pT[(e4 * 4 + 3) * 260 + col] = pr[u].w;
            }

            // prefetch next (c,eb) block (in flight during compute)
            const int n = c * 4 + eb + 1;
            if (n < 8) {
                const int cn  = n >> 2;
                const int ebn = n & 3;
#pragma unroll
                for (int u = 0; u < 8; u++) {
                    const int idx = tid + u * 256;
                    pr[u] = pg4[(size_t)(cn * 256 + (idx >> 3)) * 32 + ebn * 8 + (idx & 7)];
                }
            }
            __syncthreads();   // pT ready

            const float* WcE = Wc + (eb * 32) * 16 + hg * 8;
#pragma unroll 8
            for (int e = 0; e < 32; e++) {
                const int col = j2 ^ ((e >> 2) << 2);
                const float2 pp = *(const float2*)(pT + e * 260 + col);
                const ulonglong2 w01 = *(const ulonglong2*)(WcE + e * 16);
                const ulonglong2 w23 = *(const ulonglong2*)(WcE + e * 16 + 4);
                const ull p0 = pack2(pp.x, pp.x);
                const ull p1 = pack2(pp.y, pp.y);
                ffma2(acc2[0][0], p0, w01.x);
                ffma2(acc2[0][1], p0, w01.y);
                ffma2(acc2[0][2], p0, w23.x);
                ffma2(acc2[0][3], p0, w23.y);
                ffma2(acc2[1][0], p1, w01.x);
                ffma2(acc2[1][1], p1, w01.y);
                ffma2(acc2[1][2], p1, w23.x);
                ffma2(acc2[1][3], p1, w23.y);
            }
        }

        // epilogue for this 256-j chunk
        const int jb  = c * 256 + j2;
        const int mv0 = mrow[jb];
        const int mv1 = mrow[jb + 1];
#pragma unroll
        for (int hp = 0; hp < 4; hp++) {
            const int h0 = hg * 8 + hp * 2;
            const int h1 = h0 + 1;
            const float2 v0 = unpack2(acc2[0][hp]);   // j = jb
            const float2 v1 = unpack2(acc2[1][hp]);   // j = jb+1
            const size_t r0 = ((size_t)(b * H_ + h0) * S_ + i) * S_;
            const size_t r1 = ((size_t)(b * H_ + h1) * S_ + i) * S_;
            g_RADD[r0 + jb]     = mv0 ? (v0.x + badd[h0]) * SCALE_L2E : MASKED_SCORE;
            g_RADD[r1 + jb]     = mv0 ? (v0.y + badd[h1]) * SCALE_L2E : MASKED_SCORE;
            g_RADD[r0 + jb + 1] = mv1 ? (v1.x + badd[h0]) * SCALE_L2E : MASKED_SCORE;
            g_RADD[r1 + jb + 1] = mv1 ? (v1.y + badd[h1]) * SCALE_L2E : MASKED_SCORE;
        }
    }
}

// ---------------------------------------------------------------------------
// Kernel C: fused attention (unchanged from R14).
// ---------------------------------------------------------------------------
__global__ void __launch_bounds__(256, 3) attn_kernel(float* __restrict__ out)
{
    __shared__ __align__(16) float q_s[32 * 68];   // [d][i], pre-scaled
    __shared__ __align__(16) float k_s[32 * 68];   // [d][j]
    __shared__ __align__(16) float v_s[32 * 68];   // [d][j]
    __shared__ __align__(16) float s_s[64 * 68];   // [i][j] probs

    const int b  = blockIdx.z;
    const int h  = blockIdx.y;
    const int i0 = blockIdx.x * 64;
    const int tid  = threadIdx.x;
    const int tx = tid & 15;
    const int ty = tid >> 4;

    const size_t bh = (size_t)(b * H_ + h);
    const float* kg_base = g_K + (bh * S_) * DH_;
    const float* vg_base = g_V + (bh * S_) * DH_;

    // load q tile transposed, pre-scaled
    {
        const float* qg = g_Q + (bh * S_ + i0) * DH_;
#pragma unroll
        for (int u = 0; u < 8; u++) {
            const int f = tid + u * 256;
            const int i = f >> 5;
            const int d = f & 31;
            q_s[d * 68 + i] = qg[f] * SCALE_L2E;
        }
    }

    // stage tile 0
    {
        const float4* kg4 = (const float4*)kg_base;
        const float4* vg4 = (const float4*)vg_base;
#pragma unroll
        for (int u = 0; u < 2; u++) {
            const int f4 = tid + u * 256;
            const int j  = f4 >> 3;
            const int d0 = (f4 & 7) * 4;
            const float4 kv = kg4[f4];
            const float4 vv = vg4[f4];
            k_s[(d0 + 0) * 68 + j] = kv.x;
            k_s[(d0 + 1) * 68 + j] = kv.y;
            k_s[(d0 + 2) * 68 + j] = kv.z;
            k_s[(d0 + 3) * 68 + j] = kv.w;
            v_s[(d0 + 0) * 68 + j] = vv.x;
            v_s[(d0 + 1) * 68 + j] = vv.y;
            v_s[(d0 + 2) * 68 + j] = vv.z;
            v_s[(d0 + 3) * 68 + j] = vv.w;
        }
    }
    __syncthreads();

    float m4[4], l4[4];
#pragma unroll
    for (int ii = 0; ii < 4; ii++) { m4[ii] = MASKED_SCORE; l4[ii] = 0.0f; }

    ull accJ[4][2];
#pragma unroll
    for (int a = 0; a < 4; a++) { accJ[a][0] = 0ULL; accJ[a][1] = 0ULL; }

    for (int t = 0; t < 8; t++) {
        const int j0 = t * 64;
        const bool hasn = (t < 7);

        // prefetch next k tile into registers (v loaded at stage time)
        float4 kr[2];
        if (hasn) {
            const float4* kg4 = (const float4*)(kg_base + (size_t)(j0 + 64) * DH_);
#pragma unroll
            for (int u = 0; u < 2; u++)
                kr[u] = kg4[tid + u * 256];
        }

        // prefetch RADD (mask already folded in)
        float4 r4[4];
#pragma unroll
        for (int ii = 0; ii < 4; ii++) {
            const int i = i0 + ty * 4 + ii;
            r4[ii] = *(const float4*)(g_RADD + (bh * S_ + i) * S_ + j0 + tx * 4);
        }

        // --- QK^T 64x64, FFMA2 pairs over j ---
        ull acc2[4][2];
#pragma unroll
        for (int a = 0; a < 4; a++) { acc2[a][0] = 0ULL; acc2[a][1] = 0ULL; }

#pragma unroll
        for (int d = 0; d < 32; d++) {
            float av[4];
            *(float4*)(av) = *(const float4*)(q_s + d * 68 + ty * 4);
            const ulonglong2 bq = *(const ulonglong2*)(k_s + d * 68 + tx * 4);
#pragma unroll
            for (int ii = 0; ii < 4; ii++) {
                const ull ap = pack2(av[ii], av[ii]);
                ffma2(acc2[ii][0], ap, bq.x);
                ffma2(acc2[ii][1], ap, bq.y);
            }
        }

        // --- softmax fully in registers (16-lane j-group reduction) ---
#pragma unroll
        for (int ii = 0; ii < 4; ii++) {
            const float2 p01 = unpack2(acc2[ii][0]);
            const float2 p23 = unpack2(acc2[ii][1]);
            const float x0 = p01.x + r4[ii].x;
            const float x1 = p01.y + r4[ii].y;
            const float x2 = p23.x + r4[ii].z;
            const float x3 = p23.y + r4[ii].w;

            float mx = fmaxf(fmaxf(x0, x1), fmaxf(x2, x3));
#pragma unroll
            for (int off = 8; off > 0; off >>= 1)
                mx = fmaxf(mx, __shfl_xor_sync(0xffffffffu, mx, off));

            const float m_new = fmaxf(m4[ii], mx);
            const float e0 = exp2f(x0 - m_new);
            const float e1 = exp2f(x1 - m_new);
            const float e2 = exp2f(x2 - m_new);
            const float e3 = exp2f(x3 - m_new);

            float sm = (e0 + e1) + (e2 + e3);
#pragma unroll
            for (int off = 8; off > 0; off >>= 1)
                sm += __shfl_xor_sync(0xffffffffu, sm, off);

            const float alpha = exp2f(m4[ii] - m_new);
            l4[ii] = l4[ii] * alpha + sm;
            m4[ii] = m_new;

            const ull ap = pack2(alpha, alpha);
            accJ[ii][0] = fmul2(accJ[ii][0], ap);
            accJ[ii][1] = fmul2(accJ[ii][1], ap);

            *(float4*)(s_s + (ty * 4 + ii) * 68 + tx * 4) = make_float4(e0, e1, e2, e3);
        }
        __syncthreads();   // probs visible

        // --- PV: thread = 4i x 2d, FFMA2 packed over (even j, odd j) ---
        const int ib = ty * 4;
        const int d0 = tx * 2;
#pragma unroll 4
        for (int j4 = 0; j4 < 64; j4 += 4) {
            const ulonglong2 v0 = *(const ulonglong2*)(v_s + (d0 + 0) * 68 + j4);
            const ulonglong2 v1 = *(const ulonglong2*)(v_s + (d0 + 1) * 68 + j4);
#pragma unroll
            for (int ii = 0; ii < 4; ii++) {
                const ulonglong2 pp = *(const ulonglong2*)(s_s + (ib + ii) * 68 + j4);
                ffma2(accJ[ii][0], pp.x, v0.x);
                ffma2(accJ[ii][0], pp.y, v0.y);
                ffma2(accJ[ii][1], pp.x, v1.x);
                ffma2(accJ[ii][1], pp.y, v1.y);
            }
        }

        if (hasn) {
            __syncthreads();   // all reads of k_s/v_s/s_s done
            const float4* vg4 = (const float4*)(vg_base + (size_t)(j0 + 64) * DH_);
#pragma unroll
            for (int u = 0; u < 2; u++) {
                const int f4 = tid + u * 256;
                const int j  = f4 >> 3;
                const int dd = (f4 & 7) * 4;
                const float4 vv = vg4[f4];
                k_s[(dd + 0) * 68 + j] = kr[u].x;
                k_s[(dd + 1) * 68 + j] = kr[u].y;
                k_s[(dd + 2) * 68 + j] = kr[u].z;
                k_s[(dd + 3) * 68 + j] = kr[u].w;
                v_s[(dd + 0) * 68 + j] = vv.x;
                v_s[(dd + 1) * 68 + j] = vv.y;
                v_s[(dd + 2) * 68 + j] = vv.z;
                v_s[(dd + 3) * 68 + j] = vv.w;
            }
            __syncthreads();   // new tile visible
        }
    }

    // epilogue
    const int ib = ty * 4;
    const int d0 = tx * 2;
#pragma unroll
    for (int ii = 0; ii < 4; ii++) {
        const float inv = 1.0f / l4[ii];
        const float2 o0 = unpack2(accJ[ii][0]);
        const float2 o1 = unpack2(accJ[ii][1]);
        float2 res;
        res.x = (o0.x + o0.y) * inv;
        res.y = (o1.x + o1.y) * inv;
        *(float2*)(out + ((size_t)(b * S_ + i0 + ib + ii)) * D_ + h * DH_ + d0) = res;
    }
}

// ---------------------------------------------------------------------------
extern "C" void kernel_launch(void* const* d_in, const int* in_sizes, int n_in,
                              void* d_out, int out_size)
{
    const float* x     = (const float*)d_in[0];
    const float* p     = (const float*)d_in[1];
    const int*   mask  = (const int*)  d_in[2];
    const float* Wqkv  = (const float*)d_in[3];
    const float* bqkv  = (const float*)d_in[4];
    const float* Wrqk  = (const float*)d_in[5];
    const float* brqk  = (const float*)d_in[6];
    float* out = (float*)d_out;

    (void)in_sizes; (void)n_in; (void)out_size;

    qkv_gemm_kernel<<<dim3(1536 / 128, 2048 / 128, 2), 256>>>(x, Wqkv);
    qkv_combine_kernel<<<(2048 * 1536 / 4) / 256, 256>>>(bqkv);
    radd_kernel<<<dim3(S_, B_), 256>>>(p, Wrqk, brqk, mask);
    attn_kernel<<<dim3(S_ / 64, H_, B_), 256>>>(out);
}